// round 12
// baseline (speedup 1.0000x reference)
#include <cuda_runtime.h>
#include <cuda_bf16.h>
#include <cuda_fp16.h>
#include <cstdint>

// ---------------------------------------------------------------------------
// GAT, 3 layers.
//   GEMM: mma.sync m16n8k16 bf16 (fp32 acc), 3-term bf16 split of fp32 inputs.
//         __launch_bounds__(512,2) -> 2 CTAs/SM (reg cap 64). ELR fused into
//         epilogues: layers 0/1 direct store (H=4), layer 2 two-arrival
//         atomicAdd (H=1 spans both warp halves).
//   AGG:  quarter-warp per node, fp16 messages, fp32 accum, 4-edge batch.
//         Softmax max-shift dropped (exact by shift invariance).
// ---------------------------------------------------------------------------

#define NNODES_MAX 50000
#define NEDGES_MAX 800000

__device__ __align__(16) __half g_feath[NNODES_MAX * 128];
__device__ float g_h   [NNODES_MAX * 128];
__device__ float g_el  [NNODES_MAX * 4];
__device__ float g_er  [NNODES_MAX * 4];
__device__ int   g_cnt [NNODES_MAX];
__device__ int   g_row [NNODES_MAX + 1];
__device__ int   g_bsum[64];
__device__ int   g_srcperm[NEDGES_MAX];

__device__ __align__(16) uint16_t g_whi0[128 * 128], g_wlo0[128 * 128];
__device__ __align__(16) uint16_t g_whi1[128 * 128], g_wlo1[128 * 128];
__device__ __align__(16) uint16_t g_whi2[64 * 128],  g_wlo2[64 * 128];

// ------------------------------ PTX helpers --------------------------------

#define LDSM4(r, addr)                                                        \
    asm volatile("ldmatrix.sync.aligned.m8n8.x4.shared.b16 {%0,%1,%2,%3}, [%4];" \
        : "=r"((r)[0]), "=r"((r)[1]), "=r"((r)[2]), "=r"((r)[3]) : "r"(addr))

#define MMA16816(d, a, b0, b1)                                                \
    asm volatile("mma.sync.aligned.m16n8k16.row.col.f32.bf16.bf16.f32 "       \
        "{%0,%1,%2,%3}, {%4,%5,%6,%7}, {%8,%9}, {%0,%1,%2,%3};"               \
        : "+f"((d)[0]), "+f"((d)[1]), "+f"((d)[2]), "+f"((d)[3])              \
        : "r"((a)[0]), "r"((a)[1]), "r"((a)[2]), "r"((a)[3]), "r"(b0), "r"(b1))

#define CP_ASYNC16(dst, src)                                                  \
    asm volatile("cp.async.cg.shared.global [%0], [%1], 16;"                  \
        :: "r"(dst), "l"(src))
#define CP_COMMIT() asm volatile("cp.async.commit_group;" ::: "memory")
#define CP_WAIT0()  asm volatile("cp.async.wait_group 0;" ::: "memory")

__device__ __forceinline__ uint32_t smem_u32(const void* p) {
    uint32_t a;
    asm("{ .reg .u64 t; cvta.to.shared.u64 t, %1; cvt.u32.u64 %0, t; }"
        : "=r"(a) : "l"(p));
    return a;
}

__device__ __forceinline__ void split2(float2 v, uint32_t& hi, uint32_t& lo) {
    __nv_bfloat162 h2 = __float22bfloat162_rn(v);
    float rx = v.x - __bfloat162float(h2.x);
    float ry = v.y - __bfloat162float(h2.y);
    __nv_bfloat162 l2 = __float22bfloat162_rn(make_float2(rx, ry));
    hi = *(uint32_t*)&h2;
    lo = *(uint32_t*)&l2;
}

__device__ __forceinline__ uint32_t tile_offB(int r, int k) {
    return (uint32_t)r * 256u + (uint32_t)(((k >> 3) ^ (r & 7)) << 4)
         + (uint32_t)((k & 7) << 1);
}
__device__ __forceinline__ uint32_t tile_offA(int r, int k) {
    return (uint32_t)r * 128u + (uint32_t)(((k >> 3) ^ (r & 7)) << 4)
         + (uint32_t)((k & 7) << 1);
}

// --------------------- Fused prep: W split + dst histogram -------------------
// Blocks [0,160): split all 3 W matrices. Blocks [160,...): count dst degrees.

__global__ void k_prep(const float* __restrict__ W0, const float* __restrict__ W1,
                       const float* __restrict__ W2,
                       uint16_t* __restrict__ hi0, uint16_t* __restrict__ lo0,
                       uint16_t* __restrict__ hi1, uint16_t* __restrict__ lo1,
                       uint16_t* __restrict__ hi2, uint16_t* __restrict__ lo2,
                       const int* __restrict__ dst, int* __restrict__ cnt, int E) {
    int b = blockIdx.x;
    if (b < 160) {
        int idx = b * 256 + threadIdx.x;
        const float* W;
        uint16_t *hi, *lo;
        int C, e;
        if (idx < 16384)      { W = W0; hi = hi0; lo = lo0; C = 128; e = idx; }
        else if (idx < 32768) { W = W1; hi = hi1; lo = lo1; C = 128; e = idx - 16384; }
        else if (idx < 40960) { W = W2; hi = hi2; lo = lo2; C = 64;  e = idx - 32768; }
        else return;
        int k = e / C;
        int n = e % C;
        float v = W[e];
        __nv_bfloat16 h = __float2bfloat16_rn(v);
        float r = v - __bfloat162float(h);
        __nv_bfloat16 l = __float2bfloat16_rn(r);
        uint32_t off16 = tile_offB(n, k) >> 1;
        hi[off16] = *(uint16_t*)&h;
        lo[off16] = *(uint16_t*)&l;
    } else {
        int i = (b - 160) * 256 + threadIdx.x;
        if (i < E) atomicAdd(&cnt[dst[i]], 1);
    }
}

// ------------------------------ CSR scans ----------------------------------

__global__ void k_scan1(const int* __restrict__ cnt, int* __restrict__ row,
                        int* __restrict__ bsum, int N) {
    __shared__ int sh[1024];
    int tid = threadIdx.x;
    int idx = blockIdx.x * 1024 + tid;
    int c = (idx < N) ? cnt[idx] : 0;
    sh[tid] = c;
    __syncthreads();
    #pragma unroll
    for (int off = 1; off < 1024; off <<= 1) {
        int t = (tid >= off) ? sh[tid - off] : 0;
        __syncthreads();
        sh[tid] += t;
        __syncthreads();
    }
    if (idx < N) row[idx] = sh[tid] - c;
    if (tid == 1023) bsum[blockIdx.x] = sh[1023];
}

__global__ void k_scan3(int* __restrict__ row, const int* __restrict__ bsum,
                        int* __restrict__ cursor, int N, int E) {
    __shared__ int soff;
    if (threadIdx.x == 0) {
        int s = 0;
        for (int i = 0; i < blockIdx.x; ++i) s += bsum[i];
        soff = s;
    }
    __syncthreads();
    int idx = blockIdx.x * 1024 + threadIdx.x;
    if (idx < N) {
        int v = row[idx] + soff;
        row[idx] = v;
        cursor[idx] = v;
    }
    if (idx == 0) row[N] = E;
}

__global__ void k_scatter(const int* __restrict__ src, const int* __restrict__ dst,
                          int* __restrict__ cursor, int* __restrict__ srcperm, int E) {
    int i = blockIdx.x * blockDim.x + threadIdx.x;
    if (i < E) {
        int d = dst[i];
        int pos = atomicAdd(&cursor[d], 1);
        srcperm[pos] = src[i];
    }
}

// ------------------------------ MMA GEMM ------------------------------------
// feath[N,C](fp16) = X[N,128](fp32) @ W. 512 threads, 16 warps (8M x 2N).
// EMODE: 0 = none, 1 = fused ELR H=4 (C=128), 2 = fused ELR H=1 (C=64, atomic).

template <int C, int EMODE>
__global__ void __launch_bounds__(512, 2)
k_gemm_mma(const float* __restrict__ X,
           const uint16_t* __restrict__ whi, const uint16_t* __restrict__ wlo,
           __half* __restrict__ outh,
           const float* __restrict__ al, const float* __restrict__ ar,
           float* __restrict__ el, float* __restrict__ er, int N) {
    extern __shared__ char sm[];
    constexpr int A_HI = 0;
    constexpr int A_LO = 16384;
    constexpr int B_HI = 32768;
    constexpr int BSZ  = C * 256;
    constexpr int B_LO = B_HI + BSZ;

    const int tid  = threadIdx.x;
    const int lane = tid & 31;
    const int wid  = tid >> 5;
    const int r0   = blockIdx.x * 128;
    const uint32_t sbase = smem_u32(sm);

    #pragma unroll
    for (int i = tid; i < BSZ / 16; i += 512) {
        CP_ASYNC16(sbase + B_HI + i * 16, (const char*)whi + i * 16);
        CP_ASYNC16(sbase + B_LO + i * 16, (const char*)wlo + i * 16);
    }
    CP_COMMIT();

    const int m0 = (wid & 7) * 16;
    const int n0 = (wid >> 3) * (C / 2);
    constexpr int NT = C / 32;
    const int a_row = m0 + (lane & 15);
    const uint32_t a_base = sbase + A_HI + (uint32_t)a_row * 128u;
    const int lxor = lane & 7;
    const uint32_t b_base = sbase + B_HI
        + (uint32_t)(n0 + (lane & 7) + ((lane >> 4) << 3)) * 256u;

    float acc[2 * NT][4];
    #pragma unroll
    for (int i = 0; i < 2 * NT; ++i)
        #pragma unroll
        for (int j = 0; j < 4; ++j) acc[i][j] = 0.f;

    #pragma unroll
    for (int kc = 0; kc < 2; ++kc) {
        #pragma unroll
        for (int idx = tid; idx < 128 * 32; idx += 512) {
            int m = idx >> 5;
            int k2 = idx & 31;
            int row = r0 + m;
            float2 v = (row < N)
                ? ((const float2*)X)[(size_t)row * 64 + kc * 32 + k2]
                : make_float2(0.f, 0.f);
            uint32_t hw, lw;
            split2(v, hw, lw);
            uint32_t off = tile_offA(m, k2 * 2);
            *(uint32_t*)(sm + A_HI + off) = hw;
            *(uint32_t*)(sm + A_LO + off) = lw;
        }
        if (kc == 0) CP_WAIT0();
        __syncthreads();

        #pragma unroll
        for (int ks = 0; ks < 4; ++ks) {
            uint32_t pa = (uint32_t)(((2 * ks + (lane >> 4)) ^ lxor) << 4);
            uint32_t ah[4], alr[4];
            LDSM4(ah, a_base + pa);
            LDSM4(alr, a_base + pa + 16384u);

            int kks = kc * 4 + ks;
            uint32_t pb = (uint32_t)(((2 * kks + ((lane >> 3) & 1)) ^ lxor) << 4);
            #pragma unroll
            for (int nt = 0; nt < NT; ++nt) {
                uint32_t baddr = b_base + (uint32_t)nt * 4096u + pb;
                uint32_t bh[4], bl[4];
                LDSM4(bh, baddr);
                LDSM4(bl, baddr + (uint32_t)BSZ);
                MMA16816(acc[2 * nt],     ah,  bh[0], bh[1]);
                MMA16816(acc[2 * nt],     alr, bh[0], bh[1]);
                MMA16816(acc[2 * nt],     ah,  bl[0], bl[1]);
                MMA16816(acc[2 * nt + 1], ah,  bh[2], bh[3]);
                MMA16816(acc[2 * nt + 1], alr, bh[2], bh[3]);
                MMA16816(acc[2 * nt + 1], ah,  bl[2], bl[3]);
            }
        }
        __syncthreads();
    }

    const int er_ = r0 + m0 + (lane >> 2);
    const int ec = (lane & 3) * 2;
    #pragma unroll
    for (int t = 0; t < 2 * NT; ++t) {
        int col = n0 + t * 8 + ec;
        if (er_ < N)
            *(__half2*)(outh + (size_t)er_ * C + col) =
                __floats2half2_rn(acc[t][0], acc[t][1]);
        if (er_ + 8 < N)
            *(__half2*)(outh + (size_t)(er_ + 8) * C + col) =
                __floats2half2_rn(acc[t][2], acc[t][3]);
    }

    if constexpr (EMODE == 1) {
        // C=128, H=4. Warp-half covers heads h0e, h0e+1 (head = col/32).
        const int h0e = n0 >> 5;
        float pl0a = 0.f, pl0b = 0.f, pl1a = 0.f, pl1b = 0.f;
        float pr0a = 0.f, pr0b = 0.f, pr1a = 0.f, pr1b = 0.f;
        #pragma unroll
        for (int t = 0; t < 2 * NT; ++t) {
            int col = n0 + t * 8 + ec;
            float a0 = al[col], a1 = al[col + 1];
            float b0 = ar[col], b1 = ar[col + 1];
            float s0 = acc[t][0] * a0 + acc[t][1] * a1;
            float s1 = acc[t][2] * a0 + acc[t][3] * a1;
            float q0 = acc[t][0] * b0 + acc[t][1] * b1;
            float q1 = acc[t][2] * b0 + acc[t][3] * b1;
            if (t < NT) { pl0a += s0; pl1a += s1; pr0a += q0; pr1a += q1; }
            else        { pl0b += s0; pl1b += s1; pr0b += q0; pr1b += q1; }
        }
        #pragma unroll
        for (int off = 1; off <= 2; off <<= 1) {
            pl0a += __shfl_xor_sync(0xffffffffu, pl0a, off);
            pl0b += __shfl_xor_sync(0xffffffffu, pl0b, off);
            pl1a += __shfl_xor_sync(0xffffffffu, pl1a, off);
            pl1b += __shfl_xor_sync(0xffffffffu, pl1b, off);
            pr0a += __shfl_xor_sync(0xffffffffu, pr0a, off);
            pr0b += __shfl_xor_sync(0xffffffffu, pr0b, off);
            pr1a += __shfl_xor_sync(0xffffffffu, pr1a, off);
            pr1b += __shfl_xor_sync(0xffffffffu, pr1b, off);
        }
        if ((lane & 3) == 0) {
            if (er_ < N) {
                *(float2*)(el + (size_t)er_ * 4 + h0e) = make_float2(pl0a, pl0b);
                *(float2*)(er + (size_t)er_ * 4 + h0e) = make_float2(pr0a, pr0b);
            }
            if (er_ + 8 < N) {
                *(float2*)(el + (size_t)(er_ + 8) * 4 + h0e) = make_float2(pl1a, pl1b);
                *(float2*)(er + (size_t)(er_ + 8) * 4 + h0e) = make_float2(pr1a, pr1b);
            }
        }
    }

    if constexpr (EMODE == 2) {
        // C=64, H=1: head spans both halves; two-arrival atomicAdd per row.
        float pl0 = 0.f, pl1 = 0.f, pr0 = 0.f, pr1 = 0.f;
        #pragma unroll
        for (int t = 0; t < 2 * NT; ++t) {
            int col = n0 + t * 8 + ec;
            float a0 = al[col], a1 = al[col + 1];
            float b0 = ar[col], b1 = ar[col + 1];
            pl0 += acc[t][0] * a0 + acc[t][1] * a1;
            pl1 += acc[t][2] * a0 + acc[t][3] * a1;
            pr0 += acc[t][0] * b0 + acc[t][1] * b1;
            pr1 += acc[t][2] * b0 + acc[t][3] * b1;
        }
        #pragma unroll
        for (int off = 1; off <= 2; off <<= 1) {
            pl0 += __shfl_xor_sync(0xffffffffu, pl0, off);
            pl1 += __shfl_xor_sync(0xffffffffu, pl1, off);
            pr0 += __shfl_xor_sync(0xffffffffu, pr0, off);
            pr1 += __shfl_xor_sync(0xffffffffu, pr1, off);
        }
        if ((lane & 3) == 0) {
            if (er_ < N) {
                atomicAdd(el + er_, pl0);
                atomicAdd(er + er_, pr0);
            }
            if (er_ + 8 < N) {
                atomicAdd(el + er_ + 8, pl1);
                atomicAdd(er + er_ + 8, pr1);
            }
        }
    }
}

// ------------------------------ Aggregation --------------------------------
// Quarter-warp (8 lanes) per node; fp16 messages, fp32 accum, 4-edge batch.

template <int C, int H, bool RELU>
__global__ void k_agg(const __half* __restrict__ feat, const float* __restrict__ el,
                      const float* __restrict__ er, const int* __restrict__ rowp,
                      const int* __restrict__ srcperm, const float* __restrict__ bias,
                      float* __restrict__ out, int N) {
    int node = (blockIdx.x * blockDim.x + threadIdx.x) >> 3;
    int l8 = threadIdx.x & 7;
    if (node >= N) return;
    constexpr int V = C / 8;
    constexpr int D = C / H;
    const int h0 = (l8 * V) / D;

    float erv = er[node * H + h0];
    float acc[V];
    #pragma unroll
    for (int v = 0; v < V; ++v) acc[v] = 0.f;
    float denom = 0.f;

    int s = rowp[node];
    const int send = rowp[node + 1];

    #pragma unroll 1
    for (; s + 4 <= send; s += 4) {
        int a[4];
        #pragma unroll
        for (int q = 0; q < 4; ++q) a[q] = srcperm[s + q];
        float w[4];
        #pragma unroll
        for (int q = 0; q < 4; ++q) {
            float e = el[a[q] * H + h0] + erv;
            e = (e > 0.f) ? e : 0.2f * e;
            w[q] = __expf(e);
            denom += w[q];
        }
        if constexpr (V == 16) {
            uint4 u0[4], u1[4];
            #pragma unroll
            for (int q = 0; q < 4; ++q) {
                const uint4* p = (const uint4*)(feat + (size_t)a[q] * C);
                u0[q] = p[l8 * 2];
                u1[q] = p[l8 * 2 + 1];
            }
            #pragma unroll
            for (int q = 0; q < 4; ++q) {
                const uint32_t* pu0 = (const uint32_t*)&u0[q];
                const uint32_t* pu1 = (const uint32_t*)&u1[q];
                #pragma unroll
                for (int p2 = 0; p2 < 4; ++p2) {
                    float2 fa = __half22float2(*(__half2*)&pu0[p2]);
                    float2 fb = __half22float2(*(__half2*)&pu1[p2]);
                    acc[2 * p2]     += fa.x * w[q];
                    acc[2 * p2 + 1] += fa.y * w[q];
                    acc[8 + 2 * p2]     += fb.x * w[q];
                    acc[8 + 2 * p2 + 1] += fb.y * w[q];
                }
            }
        } else {
            uint4 u[4];
            #pragma unroll
            for (int q = 0; q < 4; ++q)
                u[q] = ((const uint4*)(feat + (size_t)a[q] * C))[l8];
            #pragma unroll
            for (int q = 0; q < 4; ++q) {
                const uint32_t* pu = (const uint32_t*)&u[q];
                #pragma unroll
                for (int p2 = 0; p2 < 4; ++p2) {
                    float2 fa = __half22float2(*(__half2*)&pu[p2]);
                    acc[2 * p2]     += fa.x * w[q];
                    acc[2 * p2 + 1] += fa.y * w[q];
                }
            }
        }
    }
    for (; s < send; ++s) {
        int sn = srcperm[s];
        float e = el[sn * H + h0] + erv;
        e = (e > 0.f) ? e : 0.2f * e;
        float w = __expf(e);
        denom += w;
        if constexpr (V == 16) {
            const uint4* p = (const uint4*)(feat + (size_t)sn * C);
            uint4 u0 = p[l8 * 2], u1 = p[l8 * 2 + 1];
            const uint32_t* pu0 = (const uint32_t*)&u0;
            const uint32_t* pu1 = (const uint32_t*)&u1;
            #pragma unroll
            for (int p2 = 0; p2 < 4; ++p2) {
                float2 fa = __half22float2(*(__half2*)&pu0[p2]);
                float2 fb = __half22float2(*(__half2*)&pu1[p2]);
                acc[2 * p2]     += fa.x * w;
                acc[2 * p2 + 1] += fa.y * w;
                acc[8 + 2 * p2]     += fb.x * w;
                acc[8 + 2 * p2 + 1] += fb.y * w;
            }
        } else {
            uint4 u = ((const uint4*)(feat + (size_t)sn * C))[l8];
            const uint32_t* pu = (const uint32_t*)&u;
            #pragma unroll
            for (int p2 = 0; p2 < 4; ++p2) {
                float2 fa = __half22float2(*(__half2*)&pu[p2]);
                acc[2 * p2]     += fa.x * w;
                acc[2 * p2 + 1] += fa.y * w;
            }
        }
    }

    float inv = 1.f / fmaxf(denom, 1e-12f);
    float res[V];
    #pragma unroll
    for (int v = 0; v < V; ++v) {
        float o = acc[v] * inv + bias[l8 * V + v];
        if (RELU) o = fmaxf(o, 0.f);
        res[v] = o;
    }
    float4* o4 = (float4*)(out + (size_t)node * C + l8 * V);
    #pragma unroll
    for (int p2 = 0; p2 < V / 4; ++p2)
        o4[p2] = make_float4(res[4 * p2], res[4 * p2 + 1],
                             res[4 * p2 + 2], res[4 * p2 + 3]);
}

// ------------------------------ Host ---------------------------------------

extern "C" void kernel_launch(void* const* d_in, const int* in_sizes, int n_in,
                              void* d_out, int out_size) {
    const float* features = (const float*)d_in[0];
    const int*   src      = (const int*)d_in[1];
    const int*   dst      = (const int*)d_in[2];
    const float* W0  = (const float*)d_in[3];
    const float* al0 = (const float*)d_in[4];
    const float* ar0 = (const float*)d_in[5];
    const float* b0  = (const float*)d_in[6];
    const float* W1  = (const float*)d_in[7];
    const float* al1 = (const float*)d_in[8];
    const float* ar1 = (const float*)d_in[9];
    const float* b1  = (const float*)d_in[10];
    const float* W2  = (const float*)d_in[11];
    const float* al2 = (const float*)d_in[12];
    const float* ar2 = (const float*)d_in[13];
    const float* b2  = (const float*)d_in[14];

    const int N = in_sizes[0] / 128;
    const int E = in_sizes[1];

    __half* feath;
    float *h, *el, *er;
    int *cnt, *row, *bsum, *srcperm;
    uint16_t *whi0, *wlo0, *whi1, *wlo1, *whi2, *wlo2;
    cudaGetSymbolAddress((void**)&feath, g_feath);
    cudaGetSymbolAddress((void**)&h, g_h);
    cudaGetSymbolAddress((void**)&el, g_el);
    cudaGetSymbolAddress((void**)&er, g_er);
    cudaGetSymbolAddress((void**)&cnt, g_cnt);
    cudaGetSymbolAddress((void**)&row, g_row);
    cudaGetSymbolAddress((void**)&bsum, g_bsum);
    cudaGetSymbolAddress((void**)&srcperm, g_srcperm);
    cudaGetSymbolAddress((void**)&whi0, g_whi0);
    cudaGetSymbolAddress((void**)&wlo0, g_wlo0);
    cudaGetSymbolAddress((void**)&whi1, g_whi1);
    cudaGetSymbolAddress((void**)&wlo1, g_wlo1);
    cudaGetSymbolAddress((void**)&whi2, g_whi2);
    cudaGetSymbolAddress((void**)&wlo2, g_wlo2);

    const int smem128 = 32768 + 2 * 128 * 256; // 98304
    const int smem64  = 32768 + 2 * 64 * 256;  // 65536
    cudaFuncSetAttribute((const void*)k_gemm_mma<128, 1>,
                         cudaFuncAttributeMaxDynamicSharedMemorySize, smem128);
    cudaFuncSetAttribute((const void*)k_gemm_mma<64, 2>,
                         cudaFuncAttributeMaxDynamicSharedMemorySize, smem64);

    const int nb = (N + 1023) / 1024;
    const int gemm_blocks = (N + 127) / 128;
    const int agg_blocks = (N + 31) / 32;      // quarter-warp per node, 256 thr

    // prep(1), scan1(2), scan3(3), GEMM0(4) -- ncu capture target
    cudaMemsetAsync(cnt, 0, (size_t)N * sizeof(int));
    k_prep<<<160 + (E + 255) / 256, 256>>>(W0, W1, W2, whi0, wlo0, whi1, wlo1,
                                           whi2, wlo2, dst, cnt, E);
    k_scan1<<<nb, 1024>>>(cnt, row, bsum, N);
    k_scan3<<<nb, 1024>>>(row, bsum, cnt, N, E);

    k_gemm_mma<128, 1><<<gemm_blocks, 512, smem128>>>(
        features, whi0, wlo0, feath, al0, ar0, el, er, N);

    k_scatter<<<(E + 255) / 256, 256>>>(src, dst, cnt, srcperm, E);

    // Layer 0
    k_agg<128, 4, true><<<agg_blocks, 256>>>(feath, el, er, row, srcperm, b0, h, N);

    // Layer 1
    k_gemm_mma<128, 1><<<gemm_blocks, 512, smem128>>>(
        h, whi1, wlo1, feath, al1, ar1, el, er, N);
    k_agg<128, 4, true><<<agg_blocks, 256>>>(feath, el, er, row, srcperm, b1, h, N);

    // Layer 2 (el/er zeroed for the atomic fused ELR)
    cudaMemsetAsync(el, 0, (size_t)N * sizeof(float));
    cudaMemsetAsync(er, 0, (size_t)N * sizeof(float));
    k_gemm_mma<64, 2><<<gemm_blocks, 512, smem64>>>(
        h, whi2, wlo2, feath, al2, ar2, el, er, N);
    k_agg<64, 1, false><<<agg_blocks, 256>>>(feath, el, er, row, srcperm, b2,
                                             (float*)d_out, N);
}

// round 13
// speedup vs baseline: 1.1159x; 1.1159x over previous
#include <cuda_runtime.h>
#include <cuda_bf16.h>
#include <cuda_fp16.h>
#include <cstdint>

// ---------------------------------------------------------------------------
// GAT, 3 layers.
//   GEMM: mma.sync m16n8k16 bf16 (fp32 acc), 3-term bf16 split of fp32 inputs.
//         __launch_bounds__(512,1) -- (512,2) spilled and regressed (R12).
//         ELR fused into epilogues: layers 0/1 direct store (H=4), layer 2
//         two-arrival atomicAdd (H=1 spans both warp halves).
//   AGG:  quarter-warp per node, fp16 messages, fp32 accum, 4-edge batch.
//         Softmax max-shift dropped (exact by shift invariance).
// ---------------------------------------------------------------------------

#define NNODES_MAX 50000
#define NEDGES_MAX 800000

__device__ __align__(16) __half g_feath[NNODES_MAX * 128];
__device__ float g_h   [NNODES_MAX * 128];
__device__ float g_el  [NNODES_MAX * 4];
__device__ float g_er  [NNODES_MAX * 4];
__device__ int   g_cnt [NNODES_MAX];
__device__ int   g_row [NNODES_MAX + 1];
__device__ int   g_bsum[64];
__device__ int   g_srcperm[NEDGES_MAX];

__device__ __align__(16) uint16_t g_whi0[128 * 128], g_wlo0[128 * 128];
__device__ __align__(16) uint16_t g_whi1[128 * 128], g_wlo1[128 * 128];
__device__ __align__(16) uint16_t g_whi2[64 * 128],  g_wlo2[64 * 128];

// ------------------------------ PTX helpers --------------------------------

#define LDSM4(r, addr)                                                        \
    asm volatile("ldmatrix.sync.aligned.m8n8.x4.shared.b16 {%0,%1,%2,%3}, [%4];" \
        : "=r"((r)[0]), "=r"((r)[1]), "=r"((r)[2]), "=r"((r)[3]) : "r"(addr))

#define MMA16816(d, a, b0, b1)                                                \
    asm volatile("mma.sync.aligned.m16n8k16.row.col.f32.bf16.bf16.f32 "       \
        "{%0,%1,%2,%3}, {%4,%5,%6,%7}, {%8,%9}, {%0,%1,%2,%3};"               \
        : "+f"((d)[0]), "+f"((d)[1]), "+f"((d)[2]), "+f"((d)[3])              \
        : "r"((a)[0]), "r"((a)[1]), "r"((a)[2]), "r"((a)[3]), "r"(b0), "r"(b1))

#define CP_ASYNC16(dst, src)                                                  \
    asm volatile("cp.async.cg.shared.global [%0], [%1], 16;"                  \
        :: "r"(dst), "l"(src))
#define CP_COMMIT() asm volatile("cp.async.commit_group;" ::: "memory")
#define CP_WAIT0()  asm volatile("cp.async.wait_group 0;" ::: "memory")

__device__ __forceinline__ uint32_t smem_u32(const void* p) {
    uint32_t a;
    asm("{ .reg .u64 t; cvta.to.shared.u64 t, %1; cvt.u32.u64 %0, t; }"
        : "=r"(a) : "l"(p));
    return a;
}

__device__ __forceinline__ void split2(float2 v, uint32_t& hi, uint32_t& lo) {
    __nv_bfloat162 h2 = __float22bfloat162_rn(v);
    float rx = v.x - __bfloat162float(h2.x);
    float ry = v.y - __bfloat162float(h2.y);
    __nv_bfloat162 l2 = __float22bfloat162_rn(make_float2(rx, ry));
    hi = *(uint32_t*)&h2;
    lo = *(uint32_t*)&l2;
}

__device__ __forceinline__ uint32_t tile_offB(int r, int k) {
    return (uint32_t)r * 256u + (uint32_t)(((k >> 3) ^ (r & 7)) << 4)
         + (uint32_t)((k & 7) << 1);
}
__device__ __forceinline__ uint32_t tile_offA(int r, int k) {
    return (uint32_t)r * 128u + (uint32_t)(((k >> 3) ^ (r & 7)) << 4)
         + (uint32_t)((k & 7) << 1);
}

// --------------------- Fused prep: W split + dst histogram -------------------
// Blocks [0,160): split all 3 W matrices. Blocks [160,...): count dst degrees.

__global__ void k_prep(const float* __restrict__ W0, const float* __restrict__ W1,
                       const float* __restrict__ W2,
                       uint16_t* __restrict__ hi0, uint16_t* __restrict__ lo0,
                       uint16_t* __restrict__ hi1, uint16_t* __restrict__ lo1,
                       uint16_t* __restrict__ hi2, uint16_t* __restrict__ lo2,
                       const int* __restrict__ dst, int* __restrict__ cnt, int E) {
    int b = blockIdx.x;
    if (b < 160) {
        int idx = b * 256 + threadIdx.x;
        const float* W;
        uint16_t *hi, *lo;
        int C, e;
        if (idx < 16384)      { W = W0; hi = hi0; lo = lo0; C = 128; e = idx; }
        else if (idx < 32768) { W = W1; hi = hi1; lo = lo1; C = 128; e = idx - 16384; }
        else if (idx < 40960) { W = W2; hi = hi2; lo = lo2; C = 64;  e = idx - 32768; }
        else return;
        int k = e / C;
        int n = e % C;
        float v = W[e];
        __nv_bfloat16 h = __float2bfloat16_rn(v);
        float r = v - __bfloat162float(h);
        __nv_bfloat16 l = __float2bfloat16_rn(r);
        uint32_t off16 = tile_offB(n, k) >> 1;
        hi[off16] = *(uint16_t*)&h;
        lo[off16] = *(uint16_t*)&l;
    } else {
        int i = (b - 160) * 256 + threadIdx.x;
        if (i < E) atomicAdd(&cnt[dst[i]], 1);
    }
}

// ------------------------------ CSR scans ----------------------------------

__global__ void k_scan1(const int* __restrict__ cnt, int* __restrict__ row,
                        int* __restrict__ bsum, int N) {
    __shared__ int sh[1024];
    int tid = threadIdx.x;
    int idx = blockIdx.x * 1024 + tid;
    int c = (idx < N) ? cnt[idx] : 0;
    sh[tid] = c;
    __syncthreads();
    #pragma unroll
    for (int off = 1; off < 1024; off <<= 1) {
        int t = (tid >= off) ? sh[tid - off] : 0;
        __syncthreads();
        sh[tid] += t;
        __syncthreads();
    }
    if (idx < N) row[idx] = sh[tid] - c;
    if (tid == 1023) bsum[blockIdx.x] = sh[1023];
}

__global__ void k_scan3(int* __restrict__ row, const int* __restrict__ bsum,
                        int* __restrict__ cursor, int N, int E) {
    __shared__ int soff;
    if (threadIdx.x == 0) {
        int s = 0;
        for (int i = 0; i < blockIdx.x; ++i) s += bsum[i];
        soff = s;
    }
    __syncthreads();
    int idx = blockIdx.x * 1024 + threadIdx.x;
    if (idx < N) {
        int v = row[idx] + soff;
        row[idx] = v;
        cursor[idx] = v;
    }
    if (idx == 0) row[N] = E;
}

__global__ void k_scatter(const int* __restrict__ src, const int* __restrict__ dst,
                          int* __restrict__ cursor, int* __restrict__ srcperm, int E) {
    int i = blockIdx.x * blockDim.x + threadIdx.x;
    if (i < E) {
        int d = dst[i];
        int pos = atomicAdd(&cursor[d], 1);
        srcperm[pos] = src[i];
    }
}

// ------------------------------ MMA GEMM ------------------------------------
// feath[N,C](fp16) = X[N,128](fp32) @ W. 512 threads, 16 warps (8M x 2N).
// EMODE: 0 = none, 1 = fused ELR H=4 (C=128), 2 = fused ELR H=1 (C=64, atomic).

template <int C, int EMODE>
__global__ void __launch_bounds__(512, 1)
k_gemm_mma(const float* __restrict__ X,
           const uint16_t* __restrict__ whi, const uint16_t* __restrict__ wlo,
           __half* __restrict__ outh,
           const float* __restrict__ al, const float* __restrict__ ar,
           float* __restrict__ el, float* __restrict__ er, int N) {
    extern __shared__ char sm[];
    constexpr int A_HI = 0;
    constexpr int A_LO = 16384;
    constexpr int B_HI = 32768;
    constexpr int BSZ  = C * 256;
    constexpr int B_LO = B_HI + BSZ;

    const int tid  = threadIdx.x;
    const int lane = tid & 31;
    const int wid  = tid >> 5;
    const int r0   = blockIdx.x * 128;
    const uint32_t sbase = smem_u32(sm);

    #pragma unroll
    for (int i = tid; i < BSZ / 16; i += 512) {
        CP_ASYNC16(sbase + B_HI + i * 16, (const char*)whi + i * 16);
        CP_ASYNC16(sbase + B_LO + i * 16, (const char*)wlo + i * 16);
    }
    CP_COMMIT();

    const int m0 = (wid & 7) * 16;
    const int n0 = (wid >> 3) * (C / 2);
    constexpr int NT = C / 32;
    const int a_row = m0 + (lane & 15);
    const uint32_t a_base = sbase + A_HI + (uint32_t)a_row * 128u;
    const int lxor = lane & 7;
    const uint32_t b_base = sbase + B_HI
        + (uint32_t)(n0 + (lane & 7) + ((lane >> 4) << 3)) * 256u;

    float acc[2 * NT][4];
    #pragma unroll
    for (int i = 0; i < 2 * NT; ++i)
        #pragma unroll
        for (int j = 0; j < 4; ++j) acc[i][j] = 0.f;

    #pragma unroll
    for (int kc = 0; kc < 2; ++kc) {
        #pragma unroll
        for (int idx = tid; idx < 128 * 32; idx += 512) {
            int m = idx >> 5;
            int k2 = idx & 31;
            int row = r0 + m;
            float2 v = (row < N)
                ? ((const float2*)X)[(size_t)row * 64 + kc * 32 + k2]
                : make_float2(0.f, 0.f);
            uint32_t hw, lw;
            split2(v, hw, lw);
            uint32_t off = tile_offA(m, k2 * 2);
            *(uint32_t*)(sm + A_HI + off) = hw;
            *(uint32_t*)(sm + A_LO + off) = lw;
        }
        if (kc == 0) CP_WAIT0();
        __syncthreads();

        #pragma unroll
        for (int ks = 0; ks < 4; ++ks) {
            uint32_t pa = (uint32_t)(((2 * ks + (lane >> 4)) ^ lxor) << 4);
            uint32_t ah[4], alr[4];
            LDSM4(ah, a_base + pa);
            LDSM4(alr, a_base + pa + 16384u);

            int kks = kc * 4 + ks;
            uint32_t pb = (uint32_t)(((2 * kks + ((lane >> 3) & 1)) ^ lxor) << 4);
            #pragma unroll
            for (int nt = 0; nt < NT; ++nt) {
                uint32_t baddr = b_base + (uint32_t)nt * 4096u + pb;
                uint32_t bh[4], bl[4];
                LDSM4(bh, baddr);
                LDSM4(bl, baddr + (uint32_t)BSZ);
                MMA16816(acc[2 * nt],     ah,  bh[0], bh[1]);
                MMA16816(acc[2 * nt],     alr, bh[0], bh[1]);
                MMA16816(acc[2 * nt],     ah,  bl[0], bl[1]);
                MMA16816(acc[2 * nt + 1], ah,  bh[2], bh[3]);
                MMA16816(acc[2 * nt + 1], alr, bh[2], bh[3]);
                MMA16816(acc[2 * nt + 1], ah,  bl[2], bl[3]);
            }
        }
        __syncthreads();
    }

    const int er_ = r0 + m0 + (lane >> 2);
    const int ec = (lane & 3) * 2;
    #pragma unroll
    for (int t = 0; t < 2 * NT; ++t) {
        int col = n0 + t * 8 + ec;
        if (er_ < N)
            *(__half2*)(outh + (size_t)er_ * C + col) =
                __floats2half2_rn(acc[t][0], acc[t][1]);
        if (er_ + 8 < N)
            *(__half2*)(outh + (size_t)(er_ + 8) * C + col) =
                __floats2half2_rn(acc[t][2], acc[t][3]);
    }

    if constexpr (EMODE == 1) {
        // C=128, H=4. Warp-half covers heads h0e, h0e+1 (head = col/32).
        const int h0e = n0 >> 5;
        float pl0a = 0.f, pl0b = 0.f, pl1a = 0.f, pl1b = 0.f;
        float pr0a = 0.f, pr0b = 0.f, pr1a = 0.f, pr1b = 0.f;
        #pragma unroll
        for (int t = 0; t < 2 * NT; ++t) {
            int col = n0 + t * 8 + ec;
            float a0 = al[col], a1 = al[col + 1];
            float b0 = ar[col], b1 = ar[col + 1];
            float s0 = acc[t][0] * a0 + acc[t][1] * a1;
            float s1 = acc[t][2] * a0 + acc[t][3] * a1;
            float q0 = acc[t][0] * b0 + acc[t][1] * b1;
            float q1 = acc[t][2] * b0 + acc[t][3] * b1;
            if (t < NT) { pl0a += s0; pl1a += s1; pr0a += q0; pr1a += q1; }
            else        { pl0b += s0; pl1b += s1; pr0b += q0; pr1b += q1; }
        }
        #pragma unroll
        for (int off = 1; off <= 2; off <<= 1) {
            pl0a += __shfl_xor_sync(0xffffffffu, pl0a, off);
            pl0b += __shfl_xor_sync(0xffffffffu, pl0b, off);
            pl1a += __shfl_xor_sync(0xffffffffu, pl1a, off);
            pl1b += __shfl_xor_sync(0xffffffffu, pl1b, off);
            pr0a += __shfl_xor_sync(0xffffffffu, pr0a, off);
            pr0b += __shfl_xor_sync(0xffffffffu, pr0b, off);
            pr1a += __shfl_xor_sync(0xffffffffu, pr1a, off);
            pr1b += __shfl_xor_sync(0xffffffffu, pr1b, off);
        }
        if ((lane & 3) == 0) {
            if (er_ < N) {
                *(float2*)(el + (size_t)er_ * 4 + h0e) = make_float2(pl0a, pl0b);
                *(float2*)(er + (size_t)er_ * 4 + h0e) = make_float2(pr0a, pr0b);
            }
            if (er_ + 8 < N) {
                *(float2*)(el + (size_t)(er_ + 8) * 4 + h0e) = make_float2(pl1a, pl1b);
                *(float2*)(er + (size_t)(er_ + 8) * 4 + h0e) = make_float2(pr1a, pr1b);
            }
        }
    }

    if constexpr (EMODE == 2) {
        // C=64, H=1: head spans both halves; two-arrival atomicAdd per row.
        float pl0 = 0.f, pl1 = 0.f, pr0 = 0.f, pr1 = 0.f;
        #pragma unroll
        for (int t = 0; t < 2 * NT; ++t) {
            int col = n0 + t * 8 + ec;
            float a0 = al[col], a1 = al[col + 1];
            float b0 = ar[col], b1 = ar[col + 1];
            pl0 += acc[t][0] * a0 + acc[t][1] * a1;
            pl1 += acc[t][2] * a0 + acc[t][3] * a1;
            pr0 += acc[t][0] * b0 + acc[t][1] * b1;
            pr1 += acc[t][2] * b0 + acc[t][3] * b1;
        }
        #pragma unroll
        for (int off = 1; off <= 2; off <<= 1) {
            pl0 += __shfl_xor_sync(0xffffffffu, pl0, off);
            pl1 += __shfl_xor_sync(0xffffffffu, pl1, off);
            pr0 += __shfl_xor_sync(0xffffffffu, pr0, off);
            pr1 += __shfl_xor_sync(0xffffffffu, pr1, off);
        }
        if ((lane & 3) == 0) {
            if (er_ < N) {
                atomicAdd(el + er_, pl0);
                atomicAdd(er + er_, pr0);
            }
            if (er_ + 8 < N) {
                atomicAdd(el + er_ + 8, pl1);
                atomicAdd(er + er_ + 8, pr1);
            }
        }
    }
}

// ------------------------------ Aggregation --------------------------------
// Quarter-warp (8 lanes) per node; fp16 messages, fp32 accum, 4-edge batch.

template <int C, int H, bool RELU>
__global__ void k_agg(const __half* __restrict__ feat, const float* __restrict__ el,
                      const float* __restrict__ er, const int* __restrict__ rowp,
                      const int* __restrict__ srcperm, const float* __restrict__ bias,
                      float* __restrict__ out, int N) {
    int node = (blockIdx.x * blockDim.x + threadIdx.x) >> 3;
    int l8 = threadIdx.x & 7;
    if (node >= N) return;
    constexpr int V = C / 8;
    constexpr int D = C / H;
    const int h0 = (l8 * V) / D;

    float erv = er[node * H + h0];
    float acc[V];
    #pragma unroll
    for (int v = 0; v < V; ++v) acc[v] = 0.f;
    float denom = 0.f;

    int s = rowp[node];
    const int send = rowp[node + 1];

    #pragma unroll 1
    for (; s + 4 <= send; s += 4) {
        int a[4];
        #pragma unroll
        for (int q = 0; q < 4; ++q) a[q] = srcperm[s + q];
        float w[4];
        #pragma unroll
        for (int q = 0; q < 4; ++q) {
            float e = el[a[q] * H + h0] + erv;
            e = (e > 0.f) ? e : 0.2f * e;
            w[q] = __expf(e);
            denom += w[q];
        }
        if constexpr (V == 16) {
            uint4 u0[4], u1[4];
            #pragma unroll
            for (int q = 0; q < 4; ++q) {
                const uint4* p = (const uint4*)(feat + (size_t)a[q] * C);
                u0[q] = p[l8 * 2];
                u1[q] = p[l8 * 2 + 1];
            }
            #pragma unroll
            for (int q = 0; q < 4; ++q) {
                const uint32_t* pu0 = (const uint32_t*)&u0[q];
                const uint32_t* pu1 = (const uint32_t*)&u1[q];
                #pragma unroll
                for (int p2 = 0; p2 < 4; ++p2) {
                    float2 fa = __half22float2(*(__half2*)&pu0[p2]);
                    float2 fb = __half22float2(*(__half2*)&pu1[p2]);
                    acc[2 * p2]     += fa.x * w[q];
                    acc[2 * p2 + 1] += fa.y * w[q];
                    acc[8 + 2 * p2]     += fb.x * w[q];
                    acc[8 + 2 * p2 + 1] += fb.y * w[q];
                }
            }
        } else {
            uint4 u[4];
            #pragma unroll
            for (int q = 0; q < 4; ++q)
                u[q] = ((const uint4*)(feat + (size_t)a[q] * C))[l8];
            #pragma unroll
            for (int q = 0; q < 4; ++q) {
                const uint32_t* pu = (const uint32_t*)&u[q];
                #pragma unroll
                for (int p2 = 0; p2 < 4; ++p2) {
                    float2 fa = __half22float2(*(__half2*)&pu[p2]);
                    acc[2 * p2]     += fa.x * w[q];
                    acc[2 * p2 + 1] += fa.y * w[q];
                }
            }
        }
    }
    for (; s < send; ++s) {
        int sn = srcperm[s];
        float e = el[sn * H + h0] + erv;
        e = (e > 0.f) ? e : 0.2f * e;
        float w = __expf(e);
        denom += w;
        if constexpr (V == 16) {
            const uint4* p = (const uint4*)(feat + (size_t)sn * C);
            uint4 u0 = p[l8 * 2], u1 = p[l8 * 2 + 1];
            const uint32_t* pu0 = (const uint32_t*)&u0;
            const uint32_t* pu1 = (const uint32_t*)&u1;
            #pragma unroll
            for (int p2 = 0; p2 < 4; ++p2) {
                float2 fa = __half22float2(*(__half2*)&pu0[p2]);
                float2 fb = __half22float2(*(__half2*)&pu1[p2]);
                acc[2 * p2]     += fa.x * w;
                acc[2 * p2 + 1] += fa.y * w;
                acc[8 + 2 * p2]     += fb.x * w;
                acc[8 + 2 * p2 + 1] += fb.y * w;
            }
        } else {
            uint4 u = ((const uint4*)(feat + (size_t)sn * C))[l8];
            const uint32_t* pu = (const uint32_t*)&u;
            #pragma unroll
            for (int p2 = 0; p2 < 4; ++p2) {
                float2 fa = __half22float2(*(__half2*)&pu[p2]);
                acc[2 * p2]     += fa.x * w;
                acc[2 * p2 + 1] += fa.y * w;
            }
        }
    }

    float inv = 1.f / fmaxf(denom, 1e-12f);
    float res[V];
    #pragma unroll
    for (int v = 0; v < V; ++v) {
        float o = acc[v] * inv + bias[l8 * V + v];
        if (RELU) o = fmaxf(o, 0.f);
        res[v] = o;
    }
    float4* o4 = (float4*)(out + (size_t)node * C + l8 * V);
    #pragma unroll
    for (int p2 = 0; p2 < V / 4; ++p2)
        o4[p2] = make_float4(res[4 * p2], res[4 * p2 + 1],
                             res[4 * p2 + 2], res[4 * p2 + 3]);
}

// ------------------------------ Host ---------------------------------------

extern "C" void kernel_launch(void* const* d_in, const int* in_sizes, int n_in,
                              void* d_out, int out_size) {
    const float* features = (const float*)d_in[0];
    const int*   src      = (const int*)d_in[1];
    const int*   dst      = (const int*)d_in[2];
    const float* W0  = (const float*)d_in[3];
    const float* al0 = (const float*)d_in[4];
    const float* ar0 = (const float*)d_in[5];
    const float* b0  = (const float*)d_in[6];
    const float* W1  = (const float*)d_in[7];
    const float* al1 = (const float*)d_in[8];
    const float* ar1 = (const float*)d_in[9];
    const float* b1  = (const float*)d_in[10];
    const float* W2  = (const float*)d_in[11];
    const float* al2 = (const float*)d_in[12];
    const float* ar2 = (const float*)d_in[13];
    const float* b2  = (const float*)d_in[14];

    const int N = in_sizes[0] / 128;
    const int E = in_sizes[1];

    __half* feath;
    float *h, *el, *er;
    int *cnt, *row, *bsum, *srcperm;
    uint16_t *whi0, *wlo0, *whi1, *wlo1, *whi2, *wlo2;
    cudaGetSymbolAddress((void**)&feath, g_feath);
    cudaGetSymbolAddress((void**)&h, g_h);
    cudaGetSymbolAddress((void**)&el, g_el);
    cudaGetSymbolAddress((void**)&er, g_er);
    cudaGetSymbolAddress((void**)&cnt, g_cnt);
    cudaGetSymbolAddress((void**)&row, g_row);
    cudaGetSymbolAddress((void**)&bsum, g_bsum);
    cudaGetSymbolAddress((void**)&srcperm, g_srcperm);
    cudaGetSymbolAddress((void**)&whi0, g_whi0);
    cudaGetSymbolAddress((void**)&wlo0, g_wlo0);
    cudaGetSymbolAddress((void**)&whi1, g_whi1);
    cudaGetSymbolAddress((void**)&wlo1, g_wlo1);
    cudaGetSymbolAddress((void**)&whi2, g_whi2);
    cudaGetSymbolAddress((void**)&wlo2, g_wlo2);

    const int smem128 = 32768 + 2 * 128 * 256; // 98304
    const int smem64  = 32768 + 2 * 64 * 256;  // 65536
    cudaFuncSetAttribute((const void*)k_gemm_mma<128, 1>,
                         cudaFuncAttributeMaxDynamicSharedMemorySize, smem128);
    cudaFuncSetAttribute((const void*)k_gemm_mma<64, 2>,
                         cudaFuncAttributeMaxDynamicSharedMemorySize, smem64);

    const int nb = (N + 1023) / 1024;
    const int gemm_blocks = (N + 127) / 128;
    const int agg_blocks = (N + 31) / 32;      // quarter-warp per node, 256 thr

    // prep(1), scan1(2), scan3(3), GEMM0(4) -- ncu capture target
    cudaMemsetAsync(cnt, 0, (size_t)N * sizeof(int));
    k_prep<<<160 + (E + 255) / 256, 256>>>(W0, W1, W2, whi0, wlo0, whi1, wlo1,
                                           whi2, wlo2, dst, cnt, E);
    k_scan1<<<nb, 1024>>>(cnt, row, bsum, N);
    k_scan3<<<nb, 1024>>>(row, bsum, cnt, N, E);

    k_gemm_mma<128, 1><<<gemm_blocks, 512, smem128>>>(
        features, whi0, wlo0, feath, al0, ar0, el, er, N);

    k_scatter<<<(E + 255) / 256, 256>>>(src, dst, cnt, srcperm, E);

    // Layer 0
    k_agg<128, 4, true><<<agg_blocks, 256>>>(feath, el, er, row, srcperm, b0, h, N);

    // Layer 1
    k_gemm_mma<128, 1><<<gemm_blocks, 512, smem128>>>(
        h, whi1, wlo1, feath, al1, ar1, el, er, N);
    k_agg<128, 4, true><<<agg_blocks, 256>>>(feath, el, er, row, srcperm, b1, h, N);

    // Layer 2 (el/er zeroed for the atomic fused ELR)
    cudaMemsetAsync(el, 0, (size_t)N * sizeof(float));
    cudaMemsetAsync(er, 0, (size_t)N * sizeof(float));
    k_gemm_mma<64, 2><<<gemm_blocks, 512, smem64>>>(
        h, whi2, wlo2, feath, al2, ar2, el, er, N);
    k_agg<64, 1, false><<<agg_blocks, 256>>>(feath, el, er, row, srcperm, b2,
                                             (float*)d_out, N);
}

// round 15
// speedup vs baseline: 1.1278x; 1.0106x over previous
#include <cuda_runtime.h>
#include <cuda_bf16.h>
#include <cuda_fp16.h>
#include <cstdint>

// ---------------------------------------------------------------------------
// GAT, 3 layers.
//   GEMM: PERSISTENT mma.sync m16n8k16 bf16 (fp32 acc), 3-term bf16 split.
//         grid = min(NBLK,148); B resident in smem across row-blocks.
//         ELR fused into epilogues: layers 0/1 direct store (H=4), layer 2
//         two-arrival atomicAdd (H=1 spans both warp halves).
//   AGG:  quarter-warp per node, fp16 messages, fp32 accum, 4-edge batch.
//         Softmax max-shift dropped (exact by shift invariance).
// ---------------------------------------------------------------------------

#define NNODES_MAX 50000
#define NEDGES_MAX 800000

__device__ __align__(16) __half g_feath[NNODES_MAX * 128];
__device__ float g_h   [NNODES_MAX * 128];
__device__ float g_el  [NNODES_MAX * 4];
__device__ float g_er  [NNODES_MAX * 4];
__device__ int   g_cnt [NNODES_MAX];
__device__ int   g_row [NNODES_MAX + 1];
__device__ int   g_bsum[64];
__device__ int   g_srcperm[NEDGES_MAX];

__device__ __align__(16) uint16_t g_whi0[128 * 128], g_wlo0[128 * 128];
__device__ __align__(16) uint16_t g_whi1[128 * 128], g_wlo1[128 * 128];
__device__ __align__(16) uint16_t g_whi2[64 * 128],  g_wlo2[64 * 128];

// ------------------------------ PTX helpers --------------------------------

#define LDSM4(r, addr)                                                        \
    asm volatile("ldmatrix.sync.aligned.m8n8.x4.shared.b16 {%0,%1,%2,%3}, [%4];" \
        : "=r"((r)[0]), "=r"((r)[1]), "=r"((r)[2]), "=r"((r)[3]) : "r"(addr))

#define MMA16816(d, a, b0, b1)                                                \
    asm volatile("mma.sync.aligned.m16n8k16.row.col.f32.bf16.bf16.f32 "       \
        "{%0,%1,%2,%3}, {%4,%5,%6,%7}, {%8,%9}, {%0,%1,%2,%3};"               \
        : "+f"((d)[0]), "+f"((d)[1]), "+f"((d)[2]), "+f"((d)[3])              \
        : "r"((a)[0]), "r"((a)[1]), "r"((a)[2]), "r"((a)[3]), "r"(b0), "r"(b1))

#define CP_ASYNC16(dst, src)                                                  \
    asm volatile("cp.async.cg.shared.global [%0], [%1], 16;"                  \
        :: "r"(dst), "l"(src))
#define CP_COMMIT() asm volatile("cp.async.commit_group;" ::: "memory")
#define CP_WAIT0()  asm volatile("cp.async.wait_group 0;" ::: "memory")

__device__ __forceinline__ uint32_t smem_u32(const void* p) {
    uint32_t a;
    asm("{ .reg .u64 t; cvta.to.shared.u64 t, %1; cvt.u32.u64 %0, t; }"
        : "=r"(a) : "l"(p));
    return a;
}

__device__ __forceinline__ void split2(float2 v, uint32_t& hi, uint32_t& lo) {
    __nv_bfloat162 h2 = __float22bfloat162_rn(v);
    float rx = v.x - __bfloat162float(h2.x);
    float ry = v.y - __bfloat162float(h2.y);
    __nv_bfloat162 l2 = __float22bfloat162_rn(make_float2(rx, ry));
    hi = *(uint32_t*)&h2;
    lo = *(uint32_t*)&l2;
}

__device__ __forceinline__ uint32_t tile_offB(int r, int k) {
    return (uint32_t)r * 256u + (uint32_t)(((k >> 3) ^ (r & 7)) << 4)
         + (uint32_t)((k & 7) << 1);
}
__device__ __forceinline__ uint32_t tile_offA(int r, int k) {
    return (uint32_t)r * 128u + (uint32_t)(((k >> 3) ^ (r & 7)) << 4)
         + (uint32_t)((k & 7) << 1);
}

// --------------------- Fused prep: W split + dst histogram -------------------

__global__ void k_prep(const float* __restrict__ W0, const float* __restrict__ W1,
                       const float* __restrict__ W2,
                       uint16_t* __restrict__ hi0, uint16_t* __restrict__ lo0,
                       uint16_t* __restrict__ hi1, uint16_t* __restrict__ lo1,
                       uint16_t* __restrict__ hi2, uint16_t* __restrict__ lo2,
                       const int* __restrict__ dst, int* __restrict__ cnt, int E) {
    int b = blockIdx.x;
    if (b < 160) {
        int idx = b * 256 + threadIdx.x;
        const float* W;
        uint16_t *hi, *lo;
        int C, e;
        if (idx < 16384)      { W = W0; hi = hi0; lo = lo0; C = 128; e = idx; }
        else if (idx < 32768) { W = W1; hi = hi1; lo = lo1; C = 128; e = idx - 16384; }
        else if (idx < 40960) { W = W2; hi = hi2; lo = lo2; C = 64;  e = idx - 32768; }
        else return;
        int k = e / C;
        int n = e % C;
        float v = W[e];
        __nv_bfloat16 h = __float2bfloat16_rn(v);
        float r = v - __bfloat162float(h);
        __nv_bfloat16 l = __float2bfloat16_rn(r);
        uint32_t off16 = tile_offB(n, k) >> 1;
        hi[off16] = *(uint16_t*)&h;
        lo[off16] = *(uint16_t*)&l;
    } else {
        int i = (b - 160) * 256 + threadIdx.x;
        if (i < E) atomicAdd(&cnt[dst[i]], 1);
    }
}

// ------------------------------ CSR scans ----------------------------------

__global__ void k_scan1(const int* __restrict__ cnt, int* __restrict__ row,
                        int* __restrict__ bsum, int N) {
    __shared__ int sh[1024];
    int tid = threadIdx.x;
    int idx = blockIdx.x * 1024 + tid;
    int c = (idx < N) ? cnt[idx] : 0;
    sh[tid] = c;
    __syncthreads();
    #pragma unroll
    for (int off = 1; off < 1024; off <<= 1) {
        int t = (tid >= off) ? sh[tid - off] : 0;
        __syncthreads();
        sh[tid] += t;
        __syncthreads();
    }
    if (idx < N) row[idx] = sh[tid] - c;
    if (tid == 1023) bsum[blockIdx.x] = sh[1023];
}

__global__ void k_scan3(int* __restrict__ row, const int* __restrict__ bsum,
                        int* __restrict__ cursor, int N, int E) {
    __shared__ int soff;
    if (threadIdx.x == 0) {
        int s = 0;
        for (int i = 0; i < blockIdx.x; ++i) s += bsum[i];
        soff = s;
    }
    __syncthreads();
    int idx = blockIdx.x * 1024 + threadIdx.x;
    if (idx < N) {
        int v = row[idx] + soff;
        row[idx] = v;
        cursor[idx] = v;
    }
    if (idx == 0) row[N] = E;
}

__global__ void k_scatter(const int* __restrict__ src, const int* __restrict__ dst,
                          int* __restrict__ cursor, int* __restrict__ srcperm, int E) {
    int i = blockIdx.x * blockDim.x + threadIdx.x;
    if (i < E) {
        int d = dst[i];
        int pos = atomicAdd(&cursor[d], 1);
        srcperm[pos] = src[i];
    }
}

// ------------------------------ Persistent MMA GEMM -------------------------
// feath[N,C](fp16) = X[N,128](fp32) @ W. 512 threads, 16 warps (8M x 2N).
// B loaded once per CTA; loop over 128-row blocks.
// EMODE: 0 = none, 1 = fused ELR H=4 (C=128), 2 = fused ELR H=1 (C=64, atomic).

template <int C, int EMODE>
__global__ void __launch_bounds__(512, 1)
k_gemm_mma(const float* __restrict__ X,
           const uint16_t* __restrict__ whi, const uint16_t* __restrict__ wlo,
           __half* __restrict__ outh,
           const float* __restrict__ al, const float* __restrict__ ar,
           float* __restrict__ el, float* __restrict__ er, int N, int nblk) {
    extern __shared__ char sm[];
    constexpr int A_HI = 0;
    constexpr int A_LO = 16384;
    constexpr int B_HI = 32768;
    constexpr int BSZ  = C * 256;
    constexpr int B_LO = B_HI + BSZ;

    const int tid  = threadIdx.x;
    const int lane = tid & 31;
    const int wid  = tid >> 5;
    const uint32_t sbase = smem_u32(sm);

    #pragma unroll
    for (int i = tid; i < BSZ / 16; i += 512) {
        CP_ASYNC16(sbase + B_HI + i * 16, (const char*)whi + i * 16);
        CP_ASYNC16(sbase + B_LO + i * 16, (const char*)wlo + i * 16);
    }
    CP_COMMIT();

    const int m0 = (wid & 7) * 16;
    const int n0 = (wid >> 3) * (C / 2);
    constexpr int NT = C / 32;
    const int a_row = m0 + (lane & 15);
    const uint32_t a_base = sbase + A_HI + (uint32_t)a_row * 128u;
    const int lxor = lane & 7;
    const uint32_t b_base = sbase + B_HI
        + (uint32_t)(n0 + (lane & 7) + ((lane >> 4) << 3)) * 256u;
    const int h0e = n0 >> 5;
    const int ec = (lane & 3) * 2;
    bool first = true;

    for (int blk = blockIdx.x; blk < nblk; blk += gridDim.x) {
        const int r0 = blk * 128;

        float acc[2 * NT][4];
        #pragma unroll
        for (int i = 0; i < 2 * NT; ++i)
            #pragma unroll
            for (int j = 0; j < 4; ++j) acc[i][j] = 0.f;

        #pragma unroll
        for (int kc = 0; kc < 2; ++kc) {
            #pragma unroll
            for (int idx = tid; idx < 128 * 32; idx += 512) {
                int m = idx >> 5;
                int k2 = idx & 31;
                int row = r0 + m;
                float2 v = (row < N)
                    ? ((const float2*)X)[(size_t)row * 64 + kc * 32 + k2]
                    : make_float2(0.f, 0.f);
                uint32_t hw, lw;
                split2(v, hw, lw);
                uint32_t off = tile_offA(m, k2 * 2);
                *(uint32_t*)(sm + A_HI + off) = hw;
                *(uint32_t*)(sm + A_LO + off) = lw;
            }
            if (first) { CP_WAIT0(); first = false; }
            __syncthreads();

            #pragma unroll
            for (int ks = 0; ks < 4; ++ks) {
                uint32_t pa = (uint32_t)(((2 * ks + (lane >> 4)) ^ lxor) << 4);
                uint32_t ah[4], alr[4];
                LDSM4(ah, a_base + pa);
                LDSM4(alr, a_base + pa + 16384u);

                int kks = kc * 4 + ks;
                uint32_t pb = (uint32_t)(((2 * kks + ((lane >> 3) & 1)) ^ lxor) << 4);
                #pragma unroll
                for (int nt = 0; nt < NT; ++nt) {
                    uint32_t baddr = b_base + (uint32_t)nt * 4096u + pb;
                    uint32_t bh[4], bl[4];
                    LDSM4(bh, baddr);
                    LDSM4(bl, baddr + (uint32_t)BSZ);
                    MMA16816(acc[2 * nt],     ah,  bh[0], bh[1]);
                    MMA16816(acc[2 * nt],     alr, bh[0], bh[1]);
                    MMA16816(acc[2 * nt],     ah,  bl[0], bl[1]);
                    MMA16816(acc[2 * nt + 1], ah,  bh[2], bh[3]);
                    MMA16816(acc[2 * nt + 1], alr, bh[2], bh[3]);
                    MMA16816(acc[2 * nt + 1], ah,  bl[2], bl[3]);
                }
            }
            __syncthreads();
        }

        const int er_ = r0 + m0 + (lane >> 2);
        #pragma unroll
        for (int t = 0; t < 2 * NT; ++t) {
            int col = n0 + t * 8 + ec;
            if (er_ < N)
                *(__half2*)(outh + (size_t)er_ * C + col) =
                    __floats2half2_rn(acc[t][0], acc[t][1]);
            if (er_ + 8 < N)
                *(__half2*)(outh + (size_t)(er_ + 8) * C + col) =
                    __floats2half2_rn(acc[t][2], acc[t][3]);
        }

        if constexpr (EMODE == 1) {
            float pl0a = 0.f, pl0b = 0.f, pl1a = 0.f, pl1b = 0.f;
            float pr0a = 0.f, pr0b = 0.f, pr1a = 0.f, pr1b = 0.f;
            #pragma unroll
            for (int t = 0; t < 2 * NT; ++t) {
                int col = n0 + t * 8 + ec;
                float a0 = al[col], a1 = al[col + 1];
                float b0 = ar[col], b1 = ar[col + 1];
                float s0 = acc[t][0] * a0 + acc[t][1] * a1;
                float s1 = acc[t][2] * a0 + acc[t][3] * a1;
                float q0 = acc[t][0] * b0 + acc[t][1] * b1;
                float q1 = acc[t][2] * b0 + acc[t][3] * b1;
                if (t < NT) { pl0a += s0; pl1a += s1; pr0a += q0; pr1a += q1; }
                else        { pl0b += s0; pl1b += s1; pr0b += q0; pr1b += q1; }
            }
            #pragma unroll
            for (int off = 1; off <= 2; off <<= 1) {
                pl0a += __shfl_xor_sync(0xffffffffu, pl0a, off);
                pl0b += __shfl_xor_sync(0xffffffffu, pl0b, off);
                pl1a += __shfl_xor_sync(0xffffffffu, pl1a, off);
                pl1b += __shfl_xor_sync(0xffffffffu, pl1b, off);
                pr0a += __shfl_xor_sync(0xffffffffu, pr0a, off);
                pr0b += __shfl_xor_sync(0xffffffffu, pr0b, off);
                pr1a += __shfl_xor_sync(0xffffffffu, pr1a, off);
                pr1b += __shfl_xor_sync(0xffffffffu, pr1b, off);
            }
            if ((lane & 3) == 0) {
                if (er_ < N) {
                    *(float2*)(el + (size_t)er_ * 4 + h0e) = make_float2(pl0a, pl0b);
                    *(float2*)(er + (size_t)er_ * 4 + h0e) = make_float2(pr0a, pr0b);
                }
                if (er_ + 8 < N) {
                    *(float2*)(el + (size_t)(er_ + 8) * 4 + h0e) = make_float2(pl1a, pl1b);
                    *(float2*)(er + (size_t)(er_ + 8) * 4 + h0e) = make_float2(pr1a, pr1b);
                }
            }
        }

        if constexpr (EMODE == 2) {
            float pl0 = 0.f, pl1 = 0.f, pr0 = 0.f, pr1 = 0.f;
            #pragma unroll
            for (int t = 0; t < 2 * NT; ++t) {
                int col = n0 + t * 8 + ec;
                float a0 = al[col], a1 = al[col + 1];
                float b0 = ar[col], b1 = ar[col + 1];
                pl0 += acc[t][0] * a0 + acc[t][1] * a1;
                pl1 += acc[t][2] * a0 + acc[t][3] * a1;
                pr0 += acc[t][0] * b0 + acc[t][1] * b1;
                pr1 += acc[t][2] * b0 + acc[t][3] * b1;
            }
            #pragma unroll
            for (int off = 1; off <= 2; off <<= 1) {
                pl0 += __shfl_xor_sync(0xffffffffu, pl0, off);
                pl1 += __shfl_xor_sync(0xffffffffu, pl1, off);
                pr0 += __shfl_xor_sync(0xffffffffu, pr0, off);
                pr1 += __shfl_xor_sync(0xffffffffu, pr1, off);
            }
            if ((lane & 3) == 0) {
                if (er_ < N) {
                    atomicAdd(el + er_, pl0);
                    atomicAdd(er + er_, pr0);
                }
                if (er_ + 8 < N) {
                    atomicAdd(el + er_ + 8, pl1);
                    atomicAdd(er + er_ + 8, pr1);
                }
            }
        }
    }
}

// ------------------------------ Aggregation --------------------------------
// Quarter-warp (8 lanes) per node; fp16 messages, fp32 accum, 4-edge batch.

template <int C, int H, bool RELU>
__global__ void k_agg(const __half* __restrict__ feat, const float* __restrict__ el,
                      const float* __restrict__ er, const int* __restrict__ rowp,
                      const int* __restrict__ srcperm, const float* __restrict__ bias,
                      float* __restrict__ out, int N) {
    int node = (blockIdx.x * blockDim.x + threadIdx.x) >> 3;
    int l8 = threadIdx.x & 7;
    if (node >= N) return;
    constexpr int V = C / 8;
    constexpr int D = C / H;
    const int h0 = (l8 * V) / D;

    float erv = er[node * H + h0];
    float acc[V];
    #pragma unroll
    for (int v = 0; v < V; ++v) acc[v] = 0.f;
    float denom = 0.f;

    int s = rowp[node];
    const int send = rowp[node + 1];

    #pragma unroll 1
    for (; s + 4 <= send; s += 4) {
        int a[4];
        #pragma unroll
        for (int q = 0; q < 4; ++q) a[q] = srcperm[s + q];
        float w[4];
        #pragma unroll
        for (int q = 0; q < 4; ++q) {
            float e = el[a[q] * H + h0] + erv;
            e = (e > 0.f) ? e : 0.2f * e;
            w[q] = __expf(e);
            denom += w[q];
        }
        if constexpr (V == 16) {
            uint4 u0[4], u1[4];
            #pragma unroll
            for (int q = 0; q < 4; ++q) {
                const uint4* p = (const uint4*)(feat + (size_t)a[q] * C);
                u0[q] = p[l8 * 2];
                u1[q] = p[l8 * 2 + 1];
            }
            #pragma unroll
            for (int q = 0; q < 4; ++q) {
                const uint32_t* pu0 = (const uint32_t*)&u0[q];
                const uint32_t* pu1 = (const uint32_t*)&u1[q];
                #pragma unroll
                for (int p2 = 0; p2 < 4; ++p2) {
                    float2 fa = __half22float2(*(__half2*)&pu0[p2]);
                    float2 fb = __half22float2(*(__half2*)&pu1[p2]);
                    acc[2 * p2]     += fa.x * w[q];
                    acc[2 * p2 + 1] += fa.y * w[q];
                    acc[8 + 2 * p2]     += fb.x * w[q];
                    acc[8 + 2 * p2 + 1] += fb.y * w[q];
                }
            }
        } else {
            uint4 u[4];
            #pragma unroll
            for (int q = 0; q < 4; ++q)
                u[q] = ((const uint4*)(feat + (size_t)a[q] * C))[l8];
            #pragma unroll
            for (int q = 0; q < 4; ++q) {
                const uint32_t* pu = (const uint32_t*)&u[q];
                #pragma unroll
                for (int p2 = 0; p2 < 4; ++p2) {
                    float2 fa = __half22float2(*(__half2*)&pu[p2]);
                    acc[2 * p2]     += fa.x * w[q];
                    acc[2 * p2 + 1] += fa.y * w[q];
                }
            }
        }
    }
    for (; s < send; ++s) {
        int sn = srcperm[s];
        float e = el[sn * H + h0] + erv;
        e = (e > 0.f) ? e : 0.2f * e;
        float w = __expf(e);
        denom += w;
        if constexpr (V == 16) {
            const uint4* p = (const uint4*)(feat + (size_t)sn * C);
            uint4 u0 = p[l8 * 2], u1 = p[l8 * 2 + 1];
            const uint32_t* pu0 = (const uint32_t*)&u0;
            const uint32_t* pu1 = (const uint32_t*)&u1;
            #pragma unroll
            for (int p2 = 0; p2 < 4; ++p2) {
                float2 fa = __half22float2(*(__half2*)&pu0[p2]);
                float2 fb = __half22float2(*(__half2*)&pu1[p2]);
                acc[2 * p2]     += fa.x * w;
                acc[2 * p2 + 1] += fa.y * w;
                acc[8 + 2 * p2]     += fb.x * w;
                acc[8 + 2 * p2 + 1] += fb.y * w;
            }
        } else {
            uint4 u = ((const uint4*)(feat + (size_t)sn * C))[l8];
            const uint32_t* pu = (const uint32_t*)&u;
            #pragma unroll
            for (int p2 = 0; p2 < 4; ++p2) {
                float2 fa = __half22float2(*(__half2*)&pu[p2]);
                acc[2 * p2]     += fa.x * w;
                acc[2 * p2 + 1] += fa.y * w;
            }
        }
    }

    float inv = 1.f / fmaxf(denom, 1e-12f);
    float res[V];
    #pragma unroll
    for (int v = 0; v < V; ++v) {
        float o = acc[v] * inv + bias[l8 * V + v];
        if (RELU) o = fmaxf(o, 0.f);
        res[v] = o;
    }
    float4* o4 = (float4*)(out + (size_t)node * C + l8 * V);
    #pragma unroll
    for (int p2 = 0; p2 < V / 4; ++p2)
        o4[p2] = make_float4(res[4 * p2], res[4 * p2 + 1],
                             res[4 * p2 + 2], res[4 * p2 + 3]);
}

// ------------------------------ Host ---------------------------------------

extern "C" void kernel_launch(void* const* d_in, const int* in_sizes, int n_in,
                              void* d_out, int out_size) {
    const float* features = (const float*)d_in[0];
    const int*   src      = (const int*)d_in[1];
    const int*   dst      = (const int*)d_in[2];
    const float* W0  = (const float*)d_in[3];
    const float* al0 = (const float*)d_in[4];
    const float* ar0 = (const float*)d_in[5];
    const float* b0  = (const float*)d_in[6];
    const float* W1  = (const float*)d_in[7];
    const float* al1 = (const float*)d_in[8];
    const float* ar1 = (const float*)d_in[9];
    const float* b1  = (const float*)d_in[10];
    const float* W2  = (const float*)d_in[11];
    const float* al2 = (const float*)d_in[12];
    const float* ar2 = (const float*)d_in[13];
    const float* b2  = (const float*)d_in[14];

    const int N = in_sizes[0] / 128;
    const int E = in_sizes[1];

    __half* feath;
    float *h, *el, *er;
    int *cnt, *row, *bsum, *srcperm;
    uint16_t *whi0, *wlo0, *whi1, *wlo1, *whi2, *wlo2;
    cudaGetSymbolAddress((void**)&feath, g_feath);
    cudaGetSymbolAddress((void**)&h, g_h);
    cudaGetSymbolAddress((void**)&el, g_el);
    cudaGetSymbolAddress((void**)&er, g_er);
    cudaGetSymbolAddress((void**)&cnt, g_cnt);
    cudaGetSymbolAddress((void**)&row, g_row);
    cudaGetSymbolAddress((void**)&bsum, g_bsum);
    cudaGetSymbolAddress((void**)&srcperm, g_srcperm);
    cudaGetSymbolAddress((void**)&whi0, g_whi0);
    cudaGetSymbolAddress((void**)&wlo0, g_wlo0);
    cudaGetSymbolAddress((void**)&whi1, g_whi1);
    cudaGetSymbolAddress((void**)&wlo1, g_wlo1);
    cudaGetSymbolAddress((void**)&whi2, g_whi2);
    cudaGetSymbolAddress((void**)&wlo2, g_wlo2);

    const int smem128 = 32768 + 2 * 128 * 256; // 98304
    const int smem64  = 32768 + 2 * 64 * 256;  // 65536
    cudaFuncSetAttribute((const void*)k_gemm_mma<128, 1>,
                         cudaFuncAttributeMaxDynamicSharedMemorySize, smem128);
    cudaFuncSetAttribute((const void*)k_gemm_mma<64, 2>,
                         cudaFuncAttributeMaxDynamicSharedMemorySize, smem64);

    const int nb = (N + 1023) / 1024;
    const int nblk = (N + 127) / 128;
    const int pgrid = (nblk < 148) ? nblk : 148;
    const int agg_blocks = (N + 31) / 32;

    // prep(1), scan1(2), scan3(3), GEMM0(4) -- ncu capture target
    cudaMemsetAsync(cnt, 0, (size_t)N * sizeof(int));
    k_prep<<<160 + (E + 255) / 256, 256>>>(W0, W1, W2, whi0, wlo0, whi1, wlo1,
                                           whi2, wlo2, dst, cnt, E);
    k_scan1<<<nb, 1024>>>(cnt, row, bsum, N);
    k_scan3<<<nb, 1024>>>(row, bsum, cnt, N, E);

    k_gemm_mma<128, 1><<<pgrid, 512, smem128>>>(
        features, whi0, wlo0, feath, al0, ar0, el, er, N, nblk);

    k_scatter<<<(E + 255) / 256, 256>>>(src, dst, cnt, srcperm, E);

    // Layer 0
    k_agg<128, 4, true><<<agg_blocks, 256>>>(feath, el, er, row, srcperm, b0, h, N);

    // Layer 1
    k_gemm_mma<128, 1><<<pgrid, 512, smem128>>>(
        h, whi1, wlo1, feath, al1, ar1, el, er, N, nblk);
    k_agg<128, 4, true><<<agg_blocks, 256>>>(feath, el, er, row, srcperm, b1, h, N);

    // Layer 2 (el/er zeroed for the atomic fused ELR)
    cudaMemsetAsync(el, 0, (size_t)N * sizeof(float));
    cudaMemsetAsync(er, 0, (size_t)N * sizeof(float));
    k_gemm_mma<64, 2><<<pgrid, 512, smem64>>>(
        h, whi2, wlo2, feath, al2, ar2, el, er, N, nblk);
    k_agg<64, 1, false><<<agg_blocks, 256>>>(feath, el, er, row, srcperm, b2,
                                             (float*)d_out, N);
}

// round 16
// speedup vs baseline: 1.1286x; 1.0007x over previous
#include <cuda_runtime.h>
#include <cuda_bf16.h>
#include <cuda_fp16.h>
#include <cstdint>

// ---------------------------------------------------------------------------
// GAT, 3 layers.
//   GEMM: PERSISTENT mma.sync m16n8k16 bf16 (fp32 acc), 3-term bf16 split,
//         SOFTWARE-PIPELINED A staging (prefetch next chunk's X into regs
//         during the current chunk's MMA). B resident in smem across blocks.
//         ELR fused into epilogues: layers 0/1 direct store (H=4), layer 2
//         two-arrival atomicAdd (H=1 spans both warp halves).
//   AGG:  quarter-warp per node, fp16 messages, fp32 accum, 4-edge batch.
//         Softmax max-shift dropped (exact by shift invariance).
// ---------------------------------------------------------------------------

#define NNODES_MAX 50000
#define NEDGES_MAX 800000

__device__ __align__(16) __half g_feath[NNODES_MAX * 128];
__device__ float g_h   [NNODES_MAX * 128];
__device__ float g_el  [NNODES_MAX * 4];
__device__ float g_er  [NNODES_MAX * 4];
__device__ int   g_cnt [NNODES_MAX];
__device__ int   g_row [NNODES_MAX + 1];
__device__ int   g_bsum[64];
__device__ int   g_srcperm[NEDGES_MAX];

__device__ __align__(16) uint16_t g_whi0[128 * 128], g_wlo0[128 * 128];
__device__ __align__(16) uint16_t g_whi1[128 * 128], g_wlo1[128 * 128];
__device__ __align__(16) uint16_t g_whi2[64 * 128],  g_wlo2[64 * 128];

// ------------------------------ PTX helpers --------------------------------

#define LDSM4(r, addr)                                                        \
    asm volatile("ldmatrix.sync.aligned.m8n8.x4.shared.b16 {%0,%1,%2,%3}, [%4];" \
        : "=r"((r)[0]), "=r"((r)[1]), "=r"((r)[2]), "=r"((r)[3]) : "r"(addr))

#define MMA16816(d, a, b0, b1)                                                \
    asm volatile("mma.sync.aligned.m16n8k16.row.col.f32.bf16.bf16.f32 "       \
        "{%0,%1,%2,%3}, {%4,%5,%6,%7}, {%8,%9}, {%0,%1,%2,%3};"               \
        : "+f"((d)[0]), "+f"((d)[1]), "+f"((d)[2]), "+f"((d)[3])              \
        : "r"((a)[0]), "r"((a)[1]), "r"((a)[2]), "r"((a)[3]), "r"(b0), "r"(b1))

#define CP_ASYNC16(dst, src)                                                  \
    asm volatile("cp.async.cg.shared.global [%0], [%1], 16;"                  \
        :: "r"(dst), "l"(src))
#define CP_COMMIT() asm volatile("cp.async.commit_group;" ::: "memory")
#define CP_WAIT0()  asm volatile("cp.async.wait_group 0;" ::: "memory")

__device__ __forceinline__ uint32_t smem_u32(const void* p) {
    uint32_t a;
    asm("{ .reg .u64 t; cvta.to.shared.u64 t, %1; cvt.u32.u64 %0, t; }"
        : "=r"(a) : "l"(p));
    return a;
}

__device__ __forceinline__ void split2(float2 v, uint32_t& hi, uint32_t& lo) {
    __nv_bfloat162 h2 = __float22bfloat162_rn(v);
    float rx = v.x - __bfloat162float(h2.x);
    float ry = v.y - __bfloat162float(h2.y);
    __nv_bfloat162 l2 = __float22bfloat162_rn(make_float2(rx, ry));
    hi = *(uint32_t*)&h2;
    lo = *(uint32_t*)&l2;
}

__device__ __forceinline__ uint32_t tile_offB(int r, int k) {
    return (uint32_t)r * 256u + (uint32_t)(((k >> 3) ^ (r & 7)) << 4)
         + (uint32_t)((k & 7) << 1);
}
__device__ __forceinline__ uint32_t tile_offA(int r, int k) {
    return (uint32_t)r * 128u + (uint32_t)(((k >> 3) ^ (r & 7)) << 4)
         + (uint32_t)((k & 7) << 1);
}

// --------------------- Fused prep: W split + dst histogram -------------------

__global__ void k_prep(const float* __restrict__ W0, const float* __restrict__ W1,
                       const float* __restrict__ W2,
                       uint16_t* __restrict__ hi0, uint16_t* __restrict__ lo0,
                       uint16_t* __restrict__ hi1, uint16_t* __restrict__ lo1,
                       uint16_t* __restrict__ hi2, uint16_t* __restrict__ lo2,
                       const int* __restrict__ dst, int* __restrict__ cnt, int E) {
    int b = blockIdx.x;
    if (b < 160) {
        int idx = b * 256 + threadIdx.x;
        const float* W;
        uint16_t *hi, *lo;
        int C, e;
        if (idx < 16384)      { W = W0; hi = hi0; lo = lo0; C = 128; e = idx; }
        else if (idx < 32768) { W = W1; hi = hi1; lo = lo1; C = 128; e = idx - 16384; }
        else if (idx < 40960) { W = W2; hi = hi2; lo = lo2; C = 64;  e = idx - 32768; }
        else return;
        int k = e / C;
        int n = e % C;
        float v = W[e];
        __nv_bfloat16 h = __float2bfloat16_rn(v);
        float r = v - __bfloat162float(h);
        __nv_bfloat16 l = __float2bfloat16_rn(r);
        uint32_t off16 = tile_offB(n, k) >> 1;
        hi[off16] = *(uint16_t*)&h;
        lo[off16] = *(uint16_t*)&l;
    } else {
        int i = (b - 160) * 256 + threadIdx.x;
        if (i < E) atomicAdd(&cnt[dst[i]], 1);
    }
}

// ------------------------------ CSR scans ----------------------------------

__global__ void k_scan1(const int* __restrict__ cnt, int* __restrict__ row,
                        int* __restrict__ bsum, int N) {
    __shared__ int sh[1024];
    int tid = threadIdx.x;
    int idx = blockIdx.x * 1024 + tid;
    int c = (idx < N) ? cnt[idx] : 0;
    sh[tid] = c;
    __syncthreads();
    #pragma unroll
    for (int off = 1; off < 1024; off <<= 1) {
        int t = (tid >= off) ? sh[tid - off] : 0;
        __syncthreads();
        sh[tid] += t;
        __syncthreads();
    }
    if (idx < N) row[idx] = sh[tid] - c;
    if (tid == 1023) bsum[blockIdx.x] = sh[1023];
}

__global__ void k_scan3(int* __restrict__ row, const int* __restrict__ bsum,
                        int* __restrict__ cursor, int N, int E) {
    __shared__ int soff;
    if (threadIdx.x == 0) {
        int s = 0;
        for (int i = 0; i < blockIdx.x; ++i) s += bsum[i];
        soff = s;
    }
    __syncthreads();
    int idx = blockIdx.x * 1024 + threadIdx.x;
    if (idx < N) {
        int v = row[idx] + soff;
        row[idx] = v;
        cursor[idx] = v;
    }
    if (idx == 0) row[N] = E;
}

__global__ void k_scatter(const int* __restrict__ src, const int* __restrict__ dst,
                          int* __restrict__ cursor, int* __restrict__ srcperm, int E) {
    int i = blockIdx.x * blockDim.x + threadIdx.x;
    if (i < E) {
        int d = dst[i];
        int pos = atomicAdd(&cursor[d], 1);
        srcperm[pos] = src[i];
    }
}

// ------------------------------ Persistent MMA GEMM -------------------------
// feath[N,C](fp16) = X[N,128](fp32) @ W. 512 threads, 16 warps (8M x 2N).
// B loaded once per CTA. A staging software-pipelined: next chunk's X is
// prefetched into registers during the current chunk's MMA.
// EMODE: 0 = none, 1 = fused ELR H=4 (C=128), 2 = fused ELR H=1 (C=64, atomic).

__device__ __forceinline__ void load_chunkA(const float* __restrict__ X, int r0,
                                            int kc, int N, float2 (&v)[8], int tid) {
    #pragma unroll
    for (int j = 0; j < 8; ++j) {
        int idx = tid + j * 512;
        int m = idx >> 5;
        int k2 = idx & 31;
        int row = r0 + m;
        v[j] = (row < N) ? ((const float2*)X)[(size_t)row * 64 + kc * 32 + k2]
                         : make_float2(0.f, 0.f);
    }
}

__device__ __forceinline__ void store_chunkA(char* sm, const float2 (&v)[8], int tid) {
    #pragma unroll
    for (int j = 0; j < 8; ++j) {
        int idx = tid + j * 512;
        int m = idx >> 5;
        int k2 = idx & 31;
        uint32_t hw, lw;
        split2(v[j], hw, lw);
        uint32_t off = tile_offA(m, k2 * 2);
        *(uint32_t*)(sm + off) = hw;
        *(uint32_t*)(sm + 16384 + off) = lw;
    }
}

template <int C, int EMODE>
__global__ void __launch_bounds__(512, 1)
k_gemm_mma(const float* __restrict__ X,
           const uint16_t* __restrict__ whi, const uint16_t* __restrict__ wlo,
           __half* __restrict__ outh,
           const float* __restrict__ al, const float* __restrict__ ar,
           float* __restrict__ el, float* __restrict__ er, int N, int nblk) {
    extern __shared__ char sm[];
    constexpr int A_HI = 0;
    constexpr int B_HI = 32768;
    constexpr int BSZ  = C * 256;

    const int tid  = threadIdx.x;
    const int lane = tid & 31;
    const int wid  = tid >> 5;
    const uint32_t sbase = smem_u32(sm);

    #pragma unroll
    for (int i = tid; i < BSZ / 16; i += 512) {
        CP_ASYNC16(sbase + B_HI + i * 16, (const char*)whi + i * 16);
        CP_ASYNC16(sbase + B_HI + BSZ + i * 16, (const char*)wlo + i * 16);
    }
    CP_COMMIT();

    const int m0 = (wid & 7) * 16;
    const int n0 = (wid >> 3) * (C / 2);
    constexpr int NT = C / 32;
    const int a_row = m0 + (lane & 15);
    const uint32_t a_base = sbase + A_HI + (uint32_t)a_row * 128u;
    const int lxor = lane & 7;
    const uint32_t b_base = sbase + B_HI
        + (uint32_t)(n0 + (lane & 7) + ((lane >> 4) << 3)) * 256u;
    const int h0e = n0 >> 5;
    const int ec = (lane & 3) * 2;
    bool first = true;

    float2 v[8];
    if (blockIdx.x < nblk)
        load_chunkA(X, blockIdx.x * 128, 0, N, v, tid);

    for (int blk = blockIdx.x; blk < nblk; blk += gridDim.x) {
        const int r0 = blk * 128;

        float acc[2 * NT][4];
        #pragma unroll
        for (int i = 0; i < 2 * NT; ++i)
            #pragma unroll
            for (int j = 0; j < 4; ++j) acc[i][j] = 0.f;

        #pragma unroll
        for (int kc = 0; kc < 2; ++kc) {
            store_chunkA(sm + A_HI, v, tid);
            if (first) { CP_WAIT0(); first = false; }
            __syncthreads();

            // prefetch next chunk while MMA runs
            {
                int pblk = (kc == 0) ? blk : blk + gridDim.x;
                int pkc = kc ^ 1;
                if (pblk < nblk)
                    load_chunkA(X, pblk * 128, pkc, N, v, tid);
            }

            #pragma unroll
            for (int ks = 0; ks < 4; ++ks) {
                uint32_t pa = (uint32_t)(((2 * ks + (lane >> 4)) ^ lxor) << 4);
                uint32_t ah[4], alr[4];
                LDSM4(ah, a_base + pa);
                LDSM4(alr, a_base + pa + 16384u);

                int kks = kc * 4 + ks;
                uint32_t pb = (uint32_t)(((2 * kks + ((lane >> 3) & 1)) ^ lxor) << 4);
                #pragma unroll
                for (int nt = 0; nt < NT; ++nt) {
                    uint32_t baddr = b_base + (uint32_t)nt * 4096u + pb;
                    uint32_t bh[4], bl[4];
                    LDSM4(bh, baddr);
                    LDSM4(bl, baddr + (uint32_t)BSZ);
                    MMA16816(acc[2 * nt],     ah,  bh[0], bh[1]);
                    MMA16816(acc[2 * nt],     alr, bh[0], bh[1]);
                    MMA16816(acc[2 * nt],     ah,  bl[0], bl[1]);
                    MMA16816(acc[2 * nt + 1], ah,  bh[2], bh[3]);
                    MMA16816(acc[2 * nt + 1], alr, bh[2], bh[3]);
                    MMA16816(acc[2 * nt + 1], ah,  bl[2], bl[3]);
                }
            }
            __syncthreads();
        }

        const int er_ = r0 + m0 + (lane >> 2);
        #pragma unroll
        for (int t = 0; t < 2 * NT; ++t) {
            int col = n0 + t * 8 + ec;
            if (er_ < N)
                *(__half2*)(outh + (size_t)er_ * C + col) =
                    __floats2half2_rn(acc[t][0], acc[t][1]);
            if (er_ + 8 < N)
                *(__half2*)(outh + (size_t)(er_ + 8) * C + col) =
                    __floats2half2_rn(acc[t][2], acc[t][3]);
        }

        if constexpr (EMODE == 1) {
            float pl0a = 0.f, pl0b = 0.f, pl1a = 0.f, pl1b = 0.f;
            float pr0a = 0.f, pr0b = 0.f, pr1a = 0.f, pr1b = 0.f;
            #pragma unroll
            for (int t = 0; t < 2 * NT; ++t) {
                int col = n0 + t * 8 + ec;
                float a0 = al[col], a1 = al[col + 1];
                float b0 = ar[col], b1 = ar[col + 1];
                float s0 = acc[t][0] * a0 + acc[t][1] * a1;
                float s1 = acc[t][2] * a0 + acc[t][3] * a1;
                float q0 = acc[t][0] * b0 + acc[t][1] * b1;
                float q1 = acc[t][2] * b0 + acc[t][3] * b1;
                if (t < NT) { pl0a += s0; pl1a += s1; pr0a += q0; pr1a += q1; }
                else        { pl0b += s0; pl1b += s1; pr0b += q0; pr1b += q1; }
            }
            #pragma unroll
            for (int off = 1; off <= 2; off <<= 1) {
                pl0a += __shfl_xor_sync(0xffffffffu, pl0a, off);
                pl0b += __shfl_xor_sync(0xffffffffu, pl0b, off);
                pl1a += __shfl_xor_sync(0xffffffffu, pl1a, off);
                pl1b += __shfl_xor_sync(0xffffffffu, pl1b, off);
                pr0a += __shfl_xor_sync(0xffffffffu, pr0a, off);
                pr0b += __shfl_xor_sync(0xffffffffu, pr0b, off);
                pr1a += __shfl_xor_sync(0xffffffffu, pr1a, off);
                pr1b += __shfl_xor_sync(0xffffffffu, pr1b, off);
            }
            if ((lane & 3) == 0) {
                if (er_ < N) {
                    *(float2*)(el + (size_t)er_ * 4 + h0e) = make_float2(pl0a, pl0b);
                    *(float2*)(er + (size_t)er_ * 4 + h0e) = make_float2(pr0a, pr0b);
                }
                if (er_ + 8 < N) {
                    *(float2*)(el + (size_t)(er_ + 8) * 4 + h0e) = make_float2(pl1a, pl1b);
                    *(float2*)(er + (size_t)(er_ + 8) * 4 + h0e) = make_float2(pr1a, pr1b);
                }
            }
        }

        if constexpr (EMODE == 2) {
            float pl0 = 0.f, pl1 = 0.f, pr0 = 0.f, pr1 = 0.f;
            #pragma unroll
            for (int t = 0; t < 2 * NT; ++t) {
                int col = n0 + t * 8 + ec;
                float a0 = al[col], a1 = al[col + 1];
                float b0 = ar[col], b1 = ar[col + 1];
                pl0 += acc[t][0] * a0 + acc[t][1] * a1;
                pl1 += acc[t][2] * a0 + acc[t][3] * a1;
                pr0 += acc[t][0] * b0 + acc[t][1] * b1;
                pr1 += acc[t][2] * b0 + acc[t][3] * b1;
            }
            #pragma unroll
            for (int off = 1; off <= 2; off <<= 1) {
                pl0 += __shfl_xor_sync(0xffffffffu, pl0, off);
                pl1 += __shfl_xor_sync(0xffffffffu, pl1, off);
                pr0 += __shfl_xor_sync(0xffffffffu, pr0, off);
                pr1 += __shfl_xor_sync(0xffffffffu, pr1, off);
            }
            if ((lane & 3) == 0) {
                if (er_ < N) {
                    atomicAdd(el + er_, pl0);
                    atomicAdd(er + er_, pr0);
                }
                if (er_ + 8 < N) {
                    atomicAdd(el + er_ + 8, pl1);
                    atomicAdd(er + er_ + 8, pr1);
                }
            }
        }
    }
}

// ------------------------------ Aggregation --------------------------------
// Quarter-warp (8 lanes) per node; fp16 messages, fp32 accum, 4-edge batch.

template <int C, int H, bool RELU>
__global__ void k_agg(const __half* __restrict__ feat, const float* __restrict__ el,
                      const float* __restrict__ er, const int* __restrict__ rowp,
                      const int* __restrict__ srcperm, const float* __restrict__ bias,
                      float* __restrict__ out, int N) {
    int node = (blockIdx.x * blockDim.x + threadIdx.x) >> 3;
    int l8 = threadIdx.x & 7;
    if (node >= N) return;
    constexpr int V = C / 8;
    constexpr int D = C / H;
    const int h0 = (l8 * V) / D;

    float erv = er[node * H + h0];
    float acc[V];
    #pragma unroll
    for (int v = 0; v < V; ++v) acc[v] = 0.f;
    float denom = 0.f;

    int s = rowp[node];
    const int send = rowp[node + 1];

    #pragma unroll 1
    for (; s + 4 <= send; s += 4) {
        int a[4];
        #pragma unroll
        for (int q = 0; q < 4; ++q) a[q] = srcperm[s + q];
        float w[4];
        #pragma unroll
        for (int q = 0; q < 4; ++q) {
            float e = el[a[q] * H + h0] + erv;
            e = (e > 0.f) ? e : 0.2f * e;
            w[q] = __expf(e);
            denom += w[q];
        }
        if constexpr (V == 16) {
            uint4 u0[4], u1[4];
            #pragma unroll
            for (int q = 0; q < 4; ++q) {
                const uint4* p = (const uint4*)(feat + (size_t)a[q] * C);
                u0[q] = p[l8 * 2];
                u1[q] = p[l8 * 2 + 1];
            }
            #pragma unroll
            for (int q = 0; q < 4; ++q) {
                const uint32_t* pu0 = (const uint32_t*)&u0[q];
                const uint32_t* pu1 = (const uint32_t*)&u1[q];
                #pragma unroll
                for (int p2 = 0; p2 < 4; ++p2) {
                    float2 fa = __half22float2(*(__half2*)&pu0[p2]);
                    float2 fb = __half22float2(*(__half2*)&pu1[p2]);
                    acc[2 * p2]     += fa.x * w[q];
                    acc[2 * p2 + 1] += fa.y * w[q];
                    acc[8 + 2 * p2]     += fb.x * w[q];
                    acc[8 + 2 * p2 + 1] += fb.y * w[q];
                }
            }
        } else {
            uint4 u[4];
            #pragma unroll
            for (int q = 0; q < 4; ++q)
                u[q] = ((const uint4*)(feat + (size_t)a[q] * C))[l8];
            #pragma unroll
            for (int q = 0; q < 4; ++q) {
                const uint32_t* pu = (const uint32_t*)&u[q];
                #pragma unroll
                for (int p2 = 0; p2 < 4; ++p2) {
                    float2 fa = __half22float2(*(__half2*)&pu[p2]);
                    acc[2 * p2]     += fa.x * w[q];
                    acc[2 * p2 + 1] += fa.y * w[q];
                }
            }
        }
    }
    for (; s < send; ++s) {
        int sn = srcperm[s];
        float e = el[sn * H + h0] + erv;
        e = (e > 0.f) ? e : 0.2f * e;
        float w = __expf(e);
        denom += w;
        if constexpr (V == 16) {
            const uint4* p = (const uint4*)(feat + (size_t)sn * C);
            uint4 u0 = p[l8 * 2], u1 = p[l8 * 2 + 1];
            const uint32_t* pu0 = (const uint32_t*)&u0;
            const uint32_t* pu1 = (const uint32_t*)&u1;
            #pragma unroll
            for (int p2 = 0; p2 < 4; ++p2) {
                float2 fa = __half22float2(*(__half2*)&pu0[p2]);
                float2 fb = __half22float2(*(__half2*)&pu1[p2]);
                acc[2 * p2]     += fa.x * w;
                acc[2 * p2 + 1] += fa.y * w;
                acc[8 + 2 * p2]     += fb.x * w;
                acc[8 + 2 * p2 + 1] += fb.y * w;
            }
        } else {
            uint4 u = ((const uint4*)(feat + (size_t)sn * C))[l8];
            const uint32_t* pu = (const uint32_t*)&u;
            #pragma unroll
            for (int p2 = 0; p2 < 4; ++p2) {
                float2 fa = __half22float2(*(__half2*)&pu[p2]);
                acc[2 * p2]     += fa.x * w;
                acc[2 * p2 + 1] += fa.y * w;
            }
        }
    }

    float inv = 1.f / fmaxf(denom, 1e-12f);
    float res[V];
    #pragma unroll
    for (int v = 0; v < V; ++v) {
        float o = acc[v] * inv + bias[l8 * V + v];
        if (RELU) o = fmaxf(o, 0.f);
        res[v] = o;
    }
    float4* o4 = (float4*)(out + (size_t)node * C + l8 * V);
    #pragma unroll
    for (int p2 = 0; p2 < V / 4; ++p2)
        o4[p2] = make_float4(res[4 * p2], res[4 * p2 + 1],
                             res[4 * p2 + 2], res[4 * p2 + 3]);
}

// ------------------------------ Host ---------------------------------------

extern "C" void kernel_launch(void* const* d_in, const int* in_sizes, int n_in,
                              void* d_out, int out_size) {
    const float* features = (const float*)d_in[0];
    const int*   src      = (const int*)d_in[1];
    const int*   dst      = (const int*)d_in[2];
    const float* W0  = (const float*)d_in[3];
    const float* al0 = (const float*)d_in[4];
    const float* ar0 = (const float*)d_in[5];
    const float* b0  = (const float*)d_in[6];
    const float* W1  = (const float*)d_in[7];
    const float* al1 = (const float*)d_in[8];
    const float* ar1 = (const float*)d_in[9];
    const float* b1  = (const float*)d_in[10];
    const float* W2  = (const float*)d_in[11];
    const float* al2 = (const float*)d_in[12];
    const float* ar2 = (const float*)d_in[13];
    const float* b2  = (const float*)d_in[14];

    const int N = in_sizes[0] / 128;
    const int E = in_sizes[1];

    __half* feath;
    float *h, *el, *er;
    int *cnt, *row, *bsum, *srcperm;
    uint16_t *whi0, *wlo0, *whi1, *wlo1, *whi2, *wlo2;
    cudaGetSymbolAddress((void**)&feath, g_feath);
    cudaGetSymbolAddress((void**)&h, g_h);
    cudaGetSymbolAddress((void**)&el, g_el);
    cudaGetSymbolAddress((void**)&er, g_er);
    cudaGetSymbolAddress((void**)&cnt, g_cnt);
    cudaGetSymbolAddress((void**)&row, g_row);
    cudaGetSymbolAddress((void**)&bsum, g_bsum);
    cudaGetSymbolAddress((void**)&srcperm, g_srcperm);
    cudaGetSymbolAddress((void**)&whi0, g_whi0);
    cudaGetSymbolAddress((void**)&wlo0, g_wlo0);
    cudaGetSymbolAddress((void**)&whi1, g_whi1);
    cudaGetSymbolAddress((void**)&wlo1, g_wlo1);
    cudaGetSymbolAddress((void**)&whi2, g_whi2);
    cudaGetSymbolAddress((void**)&wlo2, g_wlo2);

    const int smem128 = 32768 + 2 * 128 * 256; // 98304
    const int smem64  = 32768 + 2 * 64 * 256;  // 65536
    cudaFuncSetAttribute((const void*)k_gemm_mma<128, 1>,
                         cudaFuncAttributeMaxDynamicSharedMemorySize, smem128);
    cudaFuncSetAttribute((const void*)k_gemm_mma<64, 2>,
                         cudaFuncAttributeMaxDynamicSharedMemorySize, smem64);

    const int nb = (N + 1023) / 1024;
    const int nblk = (N + 127) / 128;
    const int pgrid = (nblk < 148) ? nblk : 148;
    const int agg_blocks = (N + 31) / 32;

    // prep(1), scan1(2), scan3(3), GEMM0(4) -- ncu capture target
    cudaMemsetAsync(cnt, 0, (size_t)N * sizeof(int));
    k_prep<<<160 + (E + 255) / 256, 256>>>(W0, W1, W2, whi0, wlo0, whi1, wlo1,
                                           whi2, wlo2, dst, cnt, E);
    k_scan1<<<nb, 1024>>>(cnt, row, bsum, N);
    k_scan3<<<nb, 1024>>>(row, bsum, cnt, N, E);

    k_gemm_mma<128, 1><<<pgrid, 512, smem128>>>(
        features, whi0, wlo0, feath, al0, ar0, el, er, N, nblk);

    k_scatter<<<(E + 255) / 256, 256>>>(src, dst, cnt, srcperm, E);

    // Layer 0
    k_agg<128, 4, true><<<agg_blocks, 256>>>(feath, el, er, row, srcperm, b0, h, N);

    // Layer 1
    k_gemm_mma<128, 1><<<pgrid, 512, smem128>>>(
        h, whi1, wlo1, feath, al1, ar1, el, er, N, nblk);
    k_agg<128, 4, true><<<agg_blocks, 256>>>(feath, el, er, row, srcperm, b1, h, N);

    // Layer 2 (el/er zeroed for the atomic fused ELR)
    cudaMemsetAsync(el, 0, (size_t)N * sizeof(float));
    cudaMemsetAsync(er, 0, (size_t)N * sizeof(float));
    k_gemm_mma<64, 2><<<pgrid, 512, smem64>>>(
        h, whi2, wlo2, feath, al2, ar2, el, er, N, nblk);
    k_agg<64, 1, false><<<agg_blocks, 256>>>(feath, el, er, row, srcperm, b2,
                                             (float*)d_out, N);
}

// round 17
// speedup vs baseline: 1.1292x; 1.0006x over previous
#include <cuda_runtime.h>
#include <cuda_bf16.h>
#include <cuda_fp16.h>
#include <cstdint>

// ---------------------------------------------------------------------------
// GAT, 3 layers.
//   GEMM: persistent mma.sync m16n8k16 bf16 (fp32 acc), 3-term bf16 split,
//         pipelined A staging. A input templated: fp32 (layer 0) or fp16
//         (layers 1/2 -- h stored as fp16, halving boundary traffic).
//         ELR fused into epilogues (H=4 direct store; H=1 atomicAdd).
//   AGG:  quarter-warp per node, fp16 messages, fp32 accum, 8-edge batch;
//         layers 0/1 emit fp16 h, layer 2 emits fp32 to d_out.
//         Softmax max-shift dropped (exact by shift invariance).
// ---------------------------------------------------------------------------

#define NNODES_MAX 50000
#define NEDGES_MAX 800000

__device__ __align__(16) __half g_feath[NNODES_MAX * 128];
__device__ __align__(16) __half g_hh  [NNODES_MAX * 128];
__device__ float g_el  [NNODES_MAX * 4];
__device__ float g_er  [NNODES_MAX * 4];
__device__ int   g_cnt [NNODES_MAX];
__device__ int   g_row [NNODES_MAX + 1];
__device__ int   g_bsum[64];
__device__ int   g_srcperm[NEDGES_MAX];

__device__ __align__(16) uint16_t g_whi0[128 * 128], g_wlo0[128 * 128];
__device__ __align__(16) uint16_t g_whi1[128 * 128], g_wlo1[128 * 128];
__device__ __align__(16) uint16_t g_whi2[64 * 128],  g_wlo2[64 * 128];

// ------------------------------ PTX helpers --------------------------------

#define LDSM4(r, addr)                                                        \
    asm volatile("ldmatrix.sync.aligned.m8n8.x4.shared.b16 {%0,%1,%2,%3}, [%4];" \
        : "=r"((r)[0]), "=r"((r)[1]), "=r"((r)[2]), "=r"((r)[3]) : "r"(addr))

#define MMA16816(d, a, b0, b1)                                                \
    asm volatile("mma.sync.aligned.m16n8k16.row.col.f32.bf16.bf16.f32 "       \
        "{%0,%1,%2,%3}, {%4,%5,%6,%7}, {%8,%9}, {%0,%1,%2,%3};"               \
        : "+f"((d)[0]), "+f"((d)[1]), "+f"((d)[2]), "+f"((d)[3])              \
        : "r"((a)[0]), "r"((a)[1]), "r"((a)[2]), "r"((a)[3]), "r"(b0), "r"(b1))

#define CP_ASYNC16(dst, src)                                                  \
    asm volatile("cp.async.cg.shared.global [%0], [%1], 16;"                  \
        :: "r"(dst), "l"(src))
#define CP_COMMIT() asm volatile("cp.async.commit_group;" ::: "memory")
#define CP_WAIT0()  asm volatile("cp.async.wait_group 0;" ::: "memory")

__device__ __forceinline__ uint32_t smem_u32(const void* p) {
    uint32_t a;
    asm("{ .reg .u64 t; cvta.to.shared.u64 t, %1; cvt.u32.u64 %0, t; }"
        : "=r"(a) : "l"(p));
    return a;
}

__device__ __forceinline__ void split2(float2 v, uint32_t& hi, uint32_t& lo) {
    __nv_bfloat162 h2 = __float22bfloat162_rn(v);
    float rx = v.x - __bfloat162float(h2.x);
    float ry = v.y - __bfloat162float(h2.y);
    __nv_bfloat162 l2 = __float22bfloat162_rn(make_float2(rx, ry));
    hi = *(uint32_t*)&h2;
    lo = *(uint32_t*)&l2;
}

__device__ __forceinline__ uint32_t tile_offB(int r, int k) {
    return (uint32_t)r * 256u + (uint32_t)(((k >> 3) ^ (r & 7)) << 4)
         + (uint32_t)((k & 7) << 1);
}
__device__ __forceinline__ uint32_t tile_offA(int r, int k) {
    return (uint32_t)r * 128u + (uint32_t)(((k >> 3) ^ (r & 7)) << 4)
         + (uint32_t)((k & 7) << 1);
}

// --------------------- Fused prep: W split + dst histogram -------------------

__global__ void k_prep(const float* __restrict__ W0, const float* __restrict__ W1,
                       const float* __restrict__ W2,
                       uint16_t* __restrict__ hi0, uint16_t* __restrict__ lo0,
                       uint16_t* __restrict__ hi1, uint16_t* __restrict__ lo1,
                       uint16_t* __restrict__ hi2, uint16_t* __restrict__ lo2,
                       const int* __restrict__ dst, int* __restrict__ cnt, int E) {
    int b = blockIdx.x;
    if (b < 160) {
        int idx = b * 256 + threadIdx.x;
        const float* W;
        uint16_t *hi, *lo;
        int C, e;
        if (idx < 16384)      { W = W0; hi = hi0; lo = lo0; C = 128; e = idx; }
        else if (idx < 32768) { W = W1; hi = hi1; lo = lo1; C = 128; e = idx - 16384; }
        else if (idx < 40960) { W = W2; hi = hi2; lo = lo2; C = 64;  e = idx - 32768; }
        else return;
        int k = e / C;
        int n = e % C;
        float v = W[e];
        __nv_bfloat16 h = __float2bfloat16_rn(v);
        float r = v - __bfloat162float(h);
        __nv_bfloat16 l = __float2bfloat16_rn(r);
        uint32_t off16 = tile_offB(n, k) >> 1;
        hi[off16] = *(uint16_t*)&h;
        lo[off16] = *(uint16_t*)&l;
    } else {
        int i = (b - 160) * 256 + threadIdx.x;
        if (i < E) atomicAdd(&cnt[dst[i]], 1);
    }
}

// ------------------------------ CSR scans ----------------------------------

__global__ void k_scan1(const int* __restrict__ cnt, int* __restrict__ row,
                        int* __restrict__ bsum, int N) {
    __shared__ int sh[1024];
    int tid = threadIdx.x;
    int idx = blockIdx.x * 1024 + tid;
    int c = (idx < N) ? cnt[idx] : 0;
    sh[tid] = c;
    __syncthreads();
    #pragma unroll
    for (int off = 1; off < 1024; off <<= 1) {
        int t = (tid >= off) ? sh[tid - off] : 0;
        __syncthreads();
        sh[tid] += t;
        __syncthreads();
    }
    if (idx < N) row[idx] = sh[tid] - c;
    if (tid == 1023) bsum[blockIdx.x] = sh[1023];
}

__global__ void k_scan3(int* __restrict__ row, const int* __restrict__ bsum,
                        int* __restrict__ cursor, int N, int E) {
    __shared__ int soff;
    if (threadIdx.x == 0) {
        int s = 0;
        for (int i = 0; i < blockIdx.x; ++i) s += bsum[i];
        soff = s;
    }
    __syncthreads();
    int idx = blockIdx.x * 1024 + threadIdx.x;
    if (idx < N) {
        int v = row[idx] + soff;
        row[idx] = v;
        cursor[idx] = v;
    }
    if (idx == 0) row[N] = E;
}

__global__ void k_scatter(const int* __restrict__ src, const int* __restrict__ dst,
                          int* __restrict__ cursor, int* __restrict__ srcperm, int E) {
    int i = blockIdx.x * blockDim.x + threadIdx.x;
    if (i < E) {
        int d = dst[i];
        int pos = atomicAdd(&cursor[d], 1);
        srcperm[pos] = src[i];
    }
}

// ------------------------------ Persistent MMA GEMM -------------------------
// feath[N,C](fp16) = A[N,128] @ W.  A: fp32 (layer 0) or fp16 (layers 1/2).
// 512 threads, 16 warps (8M x 2N). B resident; A staging pipelined in regs.
// EMODE: 1 = fused ELR H=4 (C=128), 2 = fused ELR H=1 (C=64, atomicAdd).

template <typename T>
__device__ __forceinline__ void load_chunkA(const T* __restrict__ X, int r0,
                                            int kc, int N, float2 (&v)[8], int tid) {
    #pragma unroll
    for (int j = 0; j < 8; ++j) {
        int idx = tid + j * 512;
        int m = idx >> 5;
        int k2 = idx & 31;
        int row = r0 + m;
        if (row < N) {
            if constexpr (sizeof(T) == 4) {
                v[j] = ((const float2*)X)[(size_t)row * 64 + kc * 32 + k2];
            } else {
                __half2 hv = ((const __half2*)X)[(size_t)row * 64 + kc * 32 + k2];
                v[j] = __half22float2(hv);
            }
        } else {
            v[j] = make_float2(0.f, 0.f);
        }
    }
}

__device__ __forceinline__ void store_chunkA(char* sm, const float2 (&v)[8], int tid) {
    #pragma unroll
    for (int j = 0; j < 8; ++j) {
        int idx = tid + j * 512;
        int m = idx >> 5;
        int k2 = idx & 31;
        uint32_t hw, lw;
        split2(v[j], hw, lw);
        uint32_t off = tile_offA(m, k2 * 2);
        *(uint32_t*)(sm + off) = hw;
        *(uint32_t*)(sm + 16384 + off) = lw;
    }
}

template <typename T, int C, int EMODE>
__global__ void __launch_bounds__(512, 1)
k_gemm_mma(const T* __restrict__ X,
           const uint16_t* __restrict__ whi, const uint16_t* __restrict__ wlo,
           __half* __restrict__ outh,
           const float* __restrict__ al, const float* __restrict__ ar,
           float* __restrict__ el, float* __restrict__ er, int N, int nblk) {
    extern __shared__ char sm[];
    constexpr int A_HI = 0;
    constexpr int B_HI = 32768;
    constexpr int BSZ  = C * 256;

    const int tid  = threadIdx.x;
    const int lane = tid & 31;
    const int wid  = tid >> 5;
    const uint32_t sbase = smem_u32(sm);

    #pragma unroll
    for (int i = tid; i < BSZ / 16; i += 512) {
        CP_ASYNC16(sbase + B_HI + i * 16, (const char*)whi + i * 16);
        CP_ASYNC16(sbase + B_HI + BSZ + i * 16, (const char*)wlo + i * 16);
    }
    CP_COMMIT();

    const int m0 = (wid & 7) * 16;
    const int n0 = (wid >> 3) * (C / 2);
    constexpr int NT = C / 32;
    const int a_row = m0 + (lane & 15);
    const uint32_t a_base = sbase + A_HI + (uint32_t)a_row * 128u;
    const int lxor = lane & 7;
    const uint32_t b_base = sbase + B_HI
        + (uint32_t)(n0 + (lane & 7) + ((lane >> 4) << 3)) * 256u;
    const int h0e = n0 >> 5;
    const int ec = (lane & 3) * 2;
    bool first = true;

    float2 v[8];
    if (blockIdx.x < nblk)
        load_chunkA(X, blockIdx.x * 128, 0, N, v, tid);

    for (int blk = blockIdx.x; blk < nblk; blk += gridDim.x) {
        const int r0 = blk * 128;

        float acc[2 * NT][4];
        #pragma unroll
        for (int i = 0; i < 2 * NT; ++i)
            #pragma unroll
            for (int j = 0; j < 4; ++j) acc[i][j] = 0.f;

        #pragma unroll
        for (int kc = 0; kc < 2; ++kc) {
            store_chunkA(sm + A_HI, v, tid);
            if (first) { CP_WAIT0(); first = false; }
            __syncthreads();

            {
                int pblk = (kc == 0) ? blk : blk + gridDim.x;
                int pkc = kc ^ 1;
                if (pblk < nblk)
                    load_chunkA(X, pblk * 128, pkc, N, v, tid);
            }

            #pragma unroll
            for (int ks = 0; ks < 4; ++ks) {
                uint32_t pa = (uint32_t)(((2 * ks + (lane >> 4)) ^ lxor) << 4);
                uint32_t ah[4], alr[4];
                LDSM4(ah, a_base + pa);
                LDSM4(alr, a_base + pa + 16384u);

                int kks = kc * 4 + ks;
                uint32_t pb = (uint32_t)(((2 * kks + ((lane >> 3) & 1)) ^ lxor) << 4);
                #pragma unroll
                for (int nt = 0; nt < NT; ++nt) {
                    uint32_t baddr = b_base + (uint32_t)nt * 4096u + pb;
                    uint32_t bh[4], bl[4];
                    LDSM4(bh, baddr);
                    LDSM4(bl, baddr + (uint32_t)BSZ);
                    MMA16816(acc[2 * nt],     ah,  bh[0], bh[1]);
                    MMA16816(acc[2 * nt],     alr, bh[0], bh[1]);
                    MMA16816(acc[2 * nt],     ah,  bl[0], bl[1]);
                    MMA16816(acc[2 * nt + 1], ah,  bh[2], bh[3]);
                    MMA16816(acc[2 * nt + 1], alr, bh[2], bh[3]);
                    MMA16816(acc[2 * nt + 1], ah,  bl[2], bl[3]);
                }
            }
            __syncthreads();
        }

        const int er_ = r0 + m0 + (lane >> 2);
        #pragma unroll
        for (int t = 0; t < 2 * NT; ++t) {
            int col = n0 + t * 8 + ec;
            if (er_ < N)
                *(__half2*)(outh + (size_t)er_ * C + col) =
                    __floats2half2_rn(acc[t][0], acc[t][1]);
            if (er_ + 8 < N)
                *(__half2*)(outh + (size_t)(er_ + 8) * C + col) =
                    __floats2half2_rn(acc[t][2], acc[t][3]);
        }

        if constexpr (EMODE == 1) {
            float pl0a = 0.f, pl0b = 0.f, pl1a = 0.f, pl1b = 0.f;
            float pr0a = 0.f, pr0b = 0.f, pr1a = 0.f, pr1b = 0.f;
            #pragma unroll
            for (int t = 0; t < 2 * NT; ++t) {
                int col = n0 + t * 8 + ec;
                float a0 = al[col], a1 = al[col + 1];
                float b0 = ar[col], b1 = ar[col + 1];
                float s0 = acc[t][0] * a0 + acc[t][1] * a1;
                float s1 = acc[t][2] * a0 + acc[t][3] * a1;
                float q0 = acc[t][0] * b0 + acc[t][1] * b1;
                float q1 = acc[t][2] * b0 + acc[t][3] * b1;
                if (t < NT) { pl0a += s0; pl1a += s1; pr0a += q0; pr1a += q1; }
                else        { pl0b += s0; pl1b += s1; pr0b += q0; pr1b += q1; }
            }
            #pragma unroll
            for (int off = 1; off <= 2; off <<= 1) {
                pl0a += __shfl_xor_sync(0xffffffffu, pl0a, off);
                pl0b += __shfl_xor_sync(0xffffffffu, pl0b, off);
                pl1a += __shfl_xor_sync(0xffffffffu, pl1a, off);
                pl1b += __shfl_xor_sync(0xffffffffu, pl1b, off);
                pr0a += __shfl_xor_sync(0xffffffffu, pr0a, off);
                pr0b += __shfl_xor_sync(0xffffffffu, pr0b, off);
                pr1a += __shfl_xor_sync(0xffffffffu, pr1a, off);
                pr1b += __shfl_xor_sync(0xffffffffu, pr1b, off);
            }
            if ((lane & 3) == 0) {
                if (er_ < N) {
                    *(float2*)(el + (size_t)er_ * 4 + h0e) = make_float2(pl0a, pl0b);
                    *(float2*)(er + (size_t)er_ * 4 + h0e) = make_float2(pr0a, pr0b);
                }
                if (er_ + 8 < N) {
                    *(float2*)(el + (size_t)(er_ + 8) * 4 + h0e) = make_float2(pl1a, pl1b);
                    *(float2*)(er + (size_t)(er_ + 8) * 4 + h0e) = make_float2(pr1a, pr1b);
                }
            }
        }

        if constexpr (EMODE == 2) {
            float pl0 = 0.f, pl1 = 0.f, pr0 = 0.f, pr1 = 0.f;
            #pragma unroll
            for (int t = 0; t < 2 * NT; ++t) {
                int col = n0 + t * 8 + ec;
                float a0 = al[col], a1 = al[col + 1];
                float b0 = ar[col], b1 = ar[col + 1];
                pl0 += acc[t][0] * a0 + acc[t][1] * a1;
                pl1 += acc[t][2] * a0 + acc[t][3] * a1;
                pr0 += acc[t][0] * b0 + acc[t][1] * b1;
                pr1 += acc[t][2] * b0 + acc[t][3] * b1;
            }
            #pragma unroll
            for (int off = 1; off <= 2; off <<= 1) {
                pl0 += __shfl_xor_sync(0xffffffffu, pl0, off);
                pl1 += __shfl_xor_sync(0xffffffffu, pl1, off);
                pr0 += __shfl_xor_sync(0xffffffffu, pr0, off);
                pr1 += __shfl_xor_sync(0xffffffffu, pr1, off);
            }
            if ((lane & 3) == 0) {
                if (er_ < N) {
                    atomicAdd(el + er_, pl0);
                    atomicAdd(er + er_, pr0);
                }
                if (er_ + 8 < N) {
                    atomicAdd(el + er_ + 8, pl1);
                    atomicAdd(er + er_ + 8, pr1);
                }
            }
        }
    }
}

// ------------------------------ Aggregation --------------------------------
// Quarter-warp (8 lanes) per node; fp16 messages, fp32 accum, 8-edge batch.
// OUT = __half (layers 0/1 -> hh) or float (layer 2 -> d_out).

template <int C, int H, bool RELU, typename OUT>
__global__ void k_agg(const __half* __restrict__ feat, const float* __restrict__ el,
                      const float* __restrict__ er, const int* __restrict__ rowp,
                      const int* __restrict__ srcperm, const float* __restrict__ bias,
                      OUT* __restrict__ out, int N) {
    int node = (blockIdx.x * blockDim.x + threadIdx.x) >> 3;
    int l8 = threadIdx.x & 7;
    if (node >= N) return;
    constexpr int V = C / 8;
    constexpr int D = C / H;
    const int h0 = (l8 * V) / D;

    float erv = er[node * H + h0];
    float acc[V];
    #pragma unroll
    for (int v = 0; v < V; ++v) acc[v] = 0.f;
    float denom = 0.f;

    int s = rowp[node];
    const int send = rowp[node + 1];

    #pragma unroll 1
    for (; s + 8 <= send; s += 8) {
        int a[8];
        #pragma unroll
        for (int q = 0; q < 8; ++q) a[q] = srcperm[s + q];
        float w[8];
        #pragma unroll
        for (int q = 0; q < 8; ++q) {
            float e = el[a[q] * H + h0] + erv;
            e = (e > 0.f) ? e : 0.2f * e;
            w[q] = __expf(e);
            denom += w[q];
        }
        #pragma unroll
        for (int g = 0; g < 2; ++g) {
            if constexpr (V == 16) {
                uint4 u0[4], u1[4];
                #pragma unroll
                for (int q = 0; q < 4; ++q) {
                    const uint4* p = (const uint4*)(feat + (size_t)a[4 * g + q] * C);
                    u0[q] = p[l8 * 2];
                    u1[q] = p[l8 * 2 + 1];
                }
                #pragma unroll
                for (int q = 0; q < 4; ++q) {
                    float wq = w[4 * g + q];
                    const uint32_t* pu0 = (const uint32_t*)&u0[q];
                    const uint32_t* pu1 = (const uint32_t*)&u1[q];
                    #pragma unroll
                    for (int p2 = 0; p2 < 4; ++p2) {
                        float2 fa = __half22float2(*(__half2*)&pu0[p2]);
                        float2 fb = __half22float2(*(__half2*)&pu1[p2]);
                        acc[2 * p2]     += fa.x * wq;
                        acc[2 * p2 + 1] += fa.y * wq;
                        acc[8 + 2 * p2]     += fb.x * wq;
                        acc[8 + 2 * p2 + 1] += fb.y * wq;
                    }
                }
            } else {
                uint4 u[4];
                #pragma unroll
                for (int q = 0; q < 4; ++q)
                    u[q] = ((const uint4*)(feat + (size_t)a[4 * g + q] * C))[l8];
                #pragma unroll
                for (int q = 0; q < 4; ++q) {
                    float wq = w[4 * g + q];
                    const uint32_t* pu = (const uint32_t*)&u[q];
                    #pragma unroll
                    for (int p2 = 0; p2 < 4; ++p2) {
                        float2 fa = __half22float2(*(__half2*)&pu[p2]);
                        acc[2 * p2]     += fa.x * wq;
                        acc[2 * p2 + 1] += fa.y * wq;
                    }
                }
            }
        }
    }
    for (; s < send; ++s) {
        int sn = srcperm[s];
        float e = el[sn * H + h0] + erv;
        e = (e > 0.f) ? e : 0.2f * e;
        float w = __expf(e);
        denom += w;
        if constexpr (V == 16) {
            const uint4* p = (const uint4*)(feat + (size_t)sn * C);
            uint4 u0 = p[l8 * 2], u1 = p[l8 * 2 + 1];
            const uint32_t* pu0 = (const uint32_t*)&u0;
            const uint32_t* pu1 = (const uint32_t*)&u1;
            #pragma unroll
            for (int p2 = 0; p2 < 4; ++p2) {
                float2 fa = __half22float2(*(__half2*)&pu0[p2]);
                float2 fb = __half22float2(*(__half2*)&pu1[p2]);
                acc[2 * p2]     += fa.x * w;
                acc[2 * p2 + 1] += fa.y * w;
                acc[8 + 2 * p2]     += fb.x * w;
                acc[8 + 2 * p2 + 1] += fb.y * w;
            }
        } else {
            uint4 u = ((const uint4*)(feat + (size_t)sn * C))[l8];
            const uint32_t* pu = (const uint32_t*)&u;
            #pragma unroll
            for (int p2 = 0; p2 < 4; ++p2) {
                float2 fa = __half22float2(*(__half2*)&pu[p2]);
                acc[2 * p2]     += fa.x * w;
                acc[2 * p2 + 1] += fa.y * w;
            }
        }
    }

    float inv = 1.f / fmaxf(denom, 1e-12f);
    float res[V];
    #pragma unroll
    for (int v = 0; v < V; ++v) {
        float o = acc[v] * inv + bias[l8 * V + v];
        if (RELU) o = fmaxf(o, 0.f);
        res[v] = o;
    }

    if constexpr (sizeof(OUT) == 2) {
        // fp16 output (V==16): 16 halves = 2 uint4 stores
        uint32_t hr[8];
        #pragma unroll
        for (int p2 = 0; p2 < V / 2; ++p2) {
            __half2 hv = __floats2half2_rn(res[2 * p2], res[2 * p2 + 1]);
            hr[p2] = *(uint32_t*)&hv;
        }
        uint4* o4 = (uint4*)((__half*)out + (size_t)node * C + l8 * V);
        o4[0] = make_uint4(hr[0], hr[1], hr[2], hr[3]);
        if constexpr (V == 16)
            o4[1] = make_uint4(hr[4], hr[5], hr[6], hr[7]);
    } else {
        float4* o4 = (float4*)((float*)out + (size_t)node * C + l8 * V);
        #pragma unroll
        for (int p2 = 0; p2 < V / 4; ++p2)
            o4[p2] = make_float4(res[4 * p2], res[4 * p2 + 1],
                                 res[4 * p2 + 2], res[4 * p2 + 3]);
    }
}

// ------------------------------ Host ---------------------------------------

extern "C" void kernel_launch(void* const* d_in, const int* in_sizes, int n_in,
                              void* d_out, int out_size) {
    const float* features = (const float*)d_in[0];
    const int*   src      = (const int*)d_in[1];
    const int*   dst      = (const int*)d_in[2];
    const float* W0  = (const float*)d_in[3];
    const float* al0 = (const float*)d_in[4];
    const float* ar0 = (const float*)d_in[5];
    const float* b0  = (const float*)d_in[6];
    const float* W1  = (const float*)d_in[7];
    const float* al1 = (const float*)d_in[8];
    const float* ar1 = (const float*)d_in[9];
    const float* b1  = (const float*)d_in[10];
    const float* W2  = (const float*)d_in[11];
    const float* al2 = (const float*)d_in[12];
    const float* ar2 = (const float*)d_in[13];
    const float* b2  = (const float*)d_in[14];

    const int N = in_sizes[0] / 128;
    const int E = in_sizes[1];

    __half *feath, *hh;
    float *el, *er;
    int *cnt, *row, *bsum, *srcperm;
    uint16_t *whi0, *wlo0, *whi1, *wlo1, *whi2, *wlo2;
    cudaGetSymbolAddress((void**)&feath, g_feath);
    cudaGetSymbolAddress((void**)&hh, g_hh);
    cudaGetSymbolAddress((void**)&el, g_el);
    cudaGetSymbolAddress((void**)&er, g_er);
    cudaGetSymbolAddress((void**)&cnt, g_cnt);
    cudaGetSymbolAddress((void**)&row, g_row);
    cudaGetSymbolAddress((void**)&bsum, g_bsum);
    cudaGetSymbolAddress((void**)&srcperm, g_srcperm);
    cudaGetSymbolAddress((void**)&whi0, g_whi0);
    cudaGetSymbolAddress((void**)&wlo0, g_wlo0);
    cudaGetSymbolAddress((void**)&whi1, g_whi1);
    cudaGetSymbolAddress((void**)&wlo1, g_wlo1);
    cudaGetSymbolAddress((void**)&whi2, g_whi2);
    cudaGetSymbolAddress((void**)&wlo2, g_wlo2);

    const int smem128 = 32768 + 2 * 128 * 256; // 98304
    const int smem64  = 32768 + 2 * 64 * 256;  // 65536
    cudaFuncSetAttribute((const void*)k_gemm_mma<float, 128, 1>,
                         cudaFuncAttributeMaxDynamicSharedMemorySize, smem128);
    cudaFuncSetAttribute((const void*)k_gemm_mma<__half, 128, 1>,
                         cudaFuncAttributeMaxDynamicSharedMemorySize, smem128);
    cudaFuncSetAttribute((const void*)k_gemm_mma<__half, 64, 2>,
                         cudaFuncAttributeMaxDynamicSharedMemorySize, smem64);

    const int nb = (N + 1023) / 1024;
    const int nblk = (N + 127) / 128;
    const int pgrid = (nblk < 148) ? nblk : 148;
    const int agg_blocks = (N + 31) / 32;

    // prep(1), scan1(2), scan3(3), GEMM0(4) -- ncu capture target
    cudaMemsetAsync(cnt, 0, (size_t)N * sizeof(int));
    k_prep<<<160 + (E + 255) / 256, 256>>>(W0, W1, W2, whi0, wlo0, whi1, wlo1,
                                           whi2, wlo2, dst, cnt, E);
    k_scan1<<<nb, 1024>>>(cnt, row, bsum, N);
    k_scan3<<<nb, 1024>>>(row, bsum, cnt, N, E);

    k_gemm_mma<float, 128, 1><<<pgrid, 512, smem128>>>(
        features, whi0, wlo0, feath, al0, ar0, el, er, N, nblk);

    k_scatter<<<(E + 255) / 256, 256>>>(src, dst, cnt, srcperm, E);

    // Layer 0 -> hh (fp16)
    k_agg<128, 4, true, __half><<<agg_blocks, 256>>>(feath, el, er, row, srcperm,
                                                     b0, hh, N);

    // Layer 1
    k_gemm_mma<__half, 128, 1><<<pgrid, 512, smem128>>>(
        hh, whi1, wlo1, feath, al1, ar1, el, er, N, nblk);
    k_agg<128, 4, true, __half><<<agg_blocks, 256>>>(feath, el, er, row, srcperm,
                                                     b1, hh, N);

    // Layer 2 (el/er zeroed for the atomic fused ELR)
    cudaMemsetAsync(el, 0, (size_t)N * sizeof(float));
    cudaMemsetAsync(er, 0, (size_t)N * sizeof(float));
    k_gemm_mma<__half, 64, 2><<<pgrid, 512, smem64>>>(
        hh, whi2, wlo2, feath, al2, ar2, el, er, N, nblk);
    k_agg<64, 1, false, float><<<agg_blocks, 256>>>(feath, el, er, row, srcperm,
                                                    b2, (float*)d_out, N);
}